// round 13
// baseline (speedup 1.0000x reference)
#include <cuda_runtime.h>
#include <cuda_fp16.h>
#include <math.h>
#include <stdint.h>

// ---------------- problem constants ----------------
#define B_   64
#define S_   100
#define D_   768
#define H_   8
#define HD_  96
#define P_   8
#define FF_  3072
#define M_   (B_ * S_)            // 6400 rows
#define NLAYERS 4
#define EPS_ 1e-5f
#define INV_SQRT_HD 0.10206207261596575f   // 1/sqrt(96)

// ---------------- device scratch ----------------
__device__ float g_x[M_ * D_];
__device__ float g_enc[M_ * D_];
__device__ float g_pbias[B_ * H_ * S_ * S_];
__device__ float g_part[4][M_ * D_];   // split-K fp32 partials
__device__ float g_pe[S_ * D_];

__device__ __half g_xq[M_ * D_];     // fp16 of attn input (layer input)
__device__ __half g_xhi[M_ * D_];    // fp16 of LN1 output (FFN1 input)
__device__ __half g_phi[M_ * D_];
__device__ __half g_plo[M_ * D_];
__device__ __half g_ffhi[(size_t)M_ * FF_];
__device__ __half g_w1h[(size_t)FF_ * D_];   // [N=3072][K=768] fp16
__device__ __half g_w2h[(size_t)D_ * FF_];   // [N=768][K=3072] fp16
__device__ __half g_wch[(size_t)D_ * D_];    // [N=768][K=768]  fp16

// ============================================================
// PTX helpers (mma.sync / ldmatrix / cp.async — all baseline sm_80+)
// ============================================================
__device__ __forceinline__ uint32_t smem_u32(const void* p) {
    uint32_t a;
    asm("{ .reg .u64 t; cvta.to.shared.u64 t, %1; cvt.u32.u64 %0, t; }" : "=r"(a) : "l"(p));
    return a;
}

#define CP_ASYNC16(dst, src) \
    asm volatile("cp.async.cg.shared.global [%0], [%1], 16;\n" :: "r"(dst), "l"(src) : "memory")
#define CP_COMMIT() asm volatile("cp.async.commit_group;\n" ::: "memory")
#define CP_WAIT0()  asm volatile("cp.async.wait_group 0;\n" ::: "memory")
#define CP_WAIT1()  asm volatile("cp.async.wait_group 1;\n" ::: "memory")

#define LDSM4(r, addr) \
    asm volatile("ldmatrix.sync.aligned.m8n8.x4.shared.b16 {%0,%1,%2,%3}, [%4];" \
        : "=r"((r)[0]), "=r"((r)[1]), "=r"((r)[2]), "=r"((r)[3]) : "r"(addr))

#define LDSM4T(r, addr) \
    asm volatile("ldmatrix.sync.aligned.m8n8.x4.trans.shared.b16 {%0,%1,%2,%3}, [%4];" \
        : "=r"((r)[0]), "=r"((r)[1]), "=r"((r)[2]), "=r"((r)[3]) : "r"(addr))

#define MMA_F16(c, a, b) \
    asm volatile("mma.sync.aligned.m16n8k16.row.col.f32.f16.f16.f32 " \
        "{%0,%1,%2,%3}, {%4,%5,%6,%7}, {%8,%9}, {%0,%1,%2,%3};" \
        : "+f"((c)[0]), "+f"((c)[1]), "+f"((c)[2]), "+f"((c)[3]) \
        : "r"((a)[0]), "r"((a)[1]), "r"((a)[2]), "r"((a)[3]), "r"((b)[0]), "r"((b)[1]))

__device__ __forceinline__ float gelu_exact(float v) {
    return 0.5f * v * (1.0f + erff(v * 0.70710678118654752f));
}
__device__ __forceinline__ void split_f16(float v, __half& h, __half& l) {
    h = __float2half(v);
    l = __float2half(v - __half2float(h));
}

// ============================================================
// GEMM: C[M,N] = A[M,K] @ B^T[N,K] (+ bias)
// TT=1: A = Ah + Al (fp16 pair); TT=0: A = Ah single fp16. B single fp16.
// EPI 1: bias + gelu -> single fp16 out. EPI 2: fp32 partial, z-indexed.
// BKS templated. 3-stage cp.async ring, 2 CTAs/SM.
// ============================================================
#define BMT 128
#define BNT 128
#define NSTAGE 3

template <int BKSv> struct GP {
    static constexpr uint32_t ROWB = BKSv * 2 + 16;
    static constexpr uint32_t MATB = 128u * ROWB;
};
#define GEMM_SMEM_T1_32 (NSTAGE * 3 * GP<32>::MATB)       // 92160 (encoder)
#define GEMM_SMEM_T0_64 (NSTAGE * 2 * GP<64>::MATB)       // 110592 (FFN)

template <int EPI, int TT, int BKSv>
__global__ __launch_bounds__(256, 2)
void mma_gemm(const __half* __restrict__ Ah_, const __half* __restrict__ Al_,
              const __half* __restrict__ Bh_,
              const float* __restrict__ bias,
              float* __restrict__ Cf, __half* __restrict__ Ch,
              int M, int N, int K)
{
    constexpr uint32_t ROWB = GP<BKSv>::ROWB;
    constexpr uint32_t MATB = GP<BKSv>::MATB;
    constexpr int NMAT = TT ? 3 : 2;
    constexpr uint32_t BUFB = NMAT * MATB;
    constexpr int CHUNKS_PER_MAT = 128 * (BKSv / 8);
    constexpr int LOAD_ITERS = NMAT * CHUNKS_PER_MAT / 256;
    constexpr int KHN = BKSv / 16;

    extern __shared__ char dsm[];
    const uint32_t sb0 = smem_u32(dsm);
    const int tid = threadIdx.x;
    const int wid = tid >> 5, lane = tid & 31;
    const int wm = wid >> 1, wn = wid & 1;
    const int row0 = blockIdx.y * BMT, col0 = blockIdx.x * BNT;
    const int Kloc = K / gridDim.z;
    const int koff = blockIdx.z * Kloc;
    const int NS = Kloc / BKSv;

    const __half* Ahp = Ah_ + koff;
    const __half* Alp = TT ? Al_ + koff : nullptr;
    const __half* Bhp = Bh_ + koff;

    float acc[2][8][4];
    #pragma unroll
    for (int i = 0; i < 2; i++)
        #pragma unroll
        for (int j = 0; j < 8; j++)
            #pragma unroll
            for (int k = 0; k < 4; k++) acc[i][j][k] = 0.f;

    const uint32_t aoff = (uint32_t)(wm * 32 + (lane & 15)) * ROWB + (uint32_t)(lane >> 4) * 16;
    const uint32_t boff = (uint32_t)(wn * 64 + ((lane >> 4) << 3) + (lane & 7)) * ROWB
                        + (uint32_t)((lane >> 3) & 1) * 16;
    const uint32_t BOFFM = (TT ? 2u : 1u) * MATB;

    auto load_step = [&](int s) {
        const uint32_t sb = sb0 + (uint32_t)(s % NSTAGE) * BUFB;
        const int k0 = s * BKSv;
        #pragma unroll
        for (int i = 0; i < LOAD_ITERS; i++) {
            int u = i * 256 + tid;
            int mat = u / CHUNKS_PER_MAT;
            int v = u % CHUNKS_PER_MAT;
            int r = v / (BKSv / 8), c = v % (BKSv / 8);
            const __half* src;
            if (TT) {
                if (mat == 0)      src = Ahp + (size_t)(row0 + r) * K + k0 + c * 8;
                else if (mat == 1) src = Alp + (size_t)(row0 + r) * K + k0 + c * 8;
                else               src = Bhp + (size_t)(col0 + r) * K + k0 + c * 8;
            } else {
                if (mat == 0)      src = Ahp + (size_t)(row0 + r) * K + k0 + c * 8;
                else               src = Bhp + (size_t)(col0 + r) * K + k0 + c * 8;
            }
            CP_ASYNC16(sb + (uint32_t)mat * MATB + (uint32_t)r * ROWB + (uint32_t)c * 16, src);
        }
        CP_COMMIT();
    };

    load_step(0);
    if (NS > 1) load_step(1);

    for (int s = 0; s < NS; s++) {
        if (s < NS - 1) { CP_WAIT1(); } else { CP_WAIT0(); }
        __syncthreads();
        if (s + 2 < NS) load_step(s + 2);

        const uint32_t sb = sb0 + (uint32_t)(s % NSTAGE) * BUFB;
        #pragma unroll
        for (int kh = 0; kh < KHN; kh++) {
            uint32_t ah[2][4], al[2][4], b[8][2];
            #pragma unroll
            for (int mf = 0; mf < 2; mf++) {
                LDSM4(ah[mf], sb + aoff + (uint32_t)(mf * 16) * ROWB + (uint32_t)kh * 32);
                if (TT) LDSM4(al[mf], sb + MATB + aoff + (uint32_t)(mf * 16) * ROWB + (uint32_t)kh * 32);
            }
            #pragma unroll
            for (int p = 0; p < 4; p++) {
                uint32_t t[4];
                LDSM4(t, sb + BOFFM + boff + (uint32_t)(p * 16) * ROWB + (uint32_t)kh * 32);
                b[2 * p][0] = t[0]; b[2 * p][1] = t[1];
                b[2 * p + 1][0] = t[2]; b[2 * p + 1][1] = t[3];
            }
            #pragma unroll
            for (int mf = 0; mf < 2; mf++)
                #pragma unroll
                for (int nf = 0; nf < 8; nf++) {
                    MMA_F16(acc[mf][nf], ah[mf], b[nf]);
                    if (TT) MMA_F16(acc[mf][nf], al[mf], b[nf]);
                }
        }
    }

    // ---- epilogue ----
    __syncthreads();
    float* stg = (float*)dsm + wid * (16 * 65);
    const int gcol0 = col0 + wn * 64;
    const float bv0 = (EPI == 2) ? 0.f : bias[gcol0 + lane];
    const float bv1 = (EPI == 2) ? 0.f : bias[gcol0 + 32 + lane];
    const int r1 = lane >> 2, c0 = (lane & 3) * 2;
    float* Cfz = (EPI == 2) ? Cf + (size_t)blockIdx.z * M * N : Cf;

    #pragma unroll
    for (int mf = 0; mf < 2; mf++) {
        #pragma unroll
        for (int nf = 0; nf < 8; nf++) {
            stg[r1 * 65 + nf * 8 + c0]           = acc[mf][nf][0];
            stg[r1 * 65 + nf * 8 + c0 + 1]       = acc[mf][nf][1];
            stg[(r1 + 8) * 65 + nf * 8 + c0]     = acc[mf][nf][2];
            stg[(r1 + 8) * 65 + nf * 8 + c0 + 1] = acc[mf][nf][3];
        }
        __syncwarp();
        const int grow = row0 + wm * 32 + mf * 16;
        #pragma unroll
        for (int r = 0; r < 16; r++) {
            float v0 = stg[r * 65 + lane] + bv0;
            float v1 = stg[r * 65 + 32 + lane] + bv1;
            if (EPI == 1) {
                v0 = gelu_exact(v0);
                v1 = gelu_exact(v1);
                size_t base = (size_t)(grow + r) * N + gcol0;
                Ch[base + lane] = __float2half(v0);
                Ch[base + 32 + lane] = __float2half(v1);
            } else {
                size_t base = (size_t)(grow + r) * N + gcol0;
                Cfz[base + lane] = v0;
                Cfz[base + 32 + lane] = v1;
            }
        }
        __syncwarp();
    }
}

// ============================================================
// weight transpose + fp16 convert
// ============================================================
__global__ void wconv_kernel(const float* __restrict__ W, __half* __restrict__ Th,
                             int K, int N) {
    __shared__ float t[32][33];
    int k0 = blockIdx.x * 32, n0 = blockIdx.y * 32;
    int tx = threadIdx.x, ty = threadIdx.y;
    #pragma unroll
    for (int i = 0; i < 4; i++)
        t[ty + i * 8][tx] = W[(size_t)(k0 + ty + i * 8) * N + n0 + tx];
    __syncthreads();
    #pragma unroll
    for (int i = 0; i < 4; i++) {
        int n = n0 + ty + i * 8, k = k0 + tx;
        Th[(size_t)n * K + k] = __float2half(t[tx][ty + i * 8]);
    }
}

// ---------------- positional-encoding table ----------------
__global__ void pe_kernel(float* __restrict__ pe) {
    int idx = blockIdx.x * 256 + threadIdx.x;
    if (idx >= S_ * D_) return;
    int d = idx % D_;
    int s = idx / D_;
    int i2 = d & ~1;
    float div = expf((float)i2 * (-9.210340371976184f / (float)D_));
    float ang = (float)s * div;
    pe[idx] = (d & 1) ? cosf(ang) : sinf(ang);
}

// ---------------- x = template + pe; also emit fp16 copy ----------------
__global__ void add_pe_kernel(const float* __restrict__ t, const float* __restrict__ pe,
                              float* __restrict__ x, __half* __restrict__ xq) {
    int idx = blockIdx.x * 256 + threadIdx.x;
    if (idx >= M_ * D_) return;
    float v = t[idx] + pe[idx % (S_ * D_)];
    x[idx] = v;
    xq[idx] = __float2half(v);
}

// ---------------- pooled = mean over P, emitted as fp16 hi/lo ----------------
__global__ void pool_kernel(const float* __restrict__ ps,
                            __half* __restrict__ ph, __half* __restrict__ pl) {
    int idx = blockIdx.x * 256 + threadIdx.x;
    if (idx >= M_ * D_) return;
    int bs = idx / D_;
    int c  = idx % D_;
    const float* base = ps + (size_t)bs * (P_ * D_) + c;
    float s = 0.f;
    #pragma unroll
    for (int p = 0; p < P_; p++) s += base[p * D_];
    float m = s * (1.0f / P_);
    __half h, l;
    split_f16(m, h, l);
    ph[idx] = h; pl[idx] = l;
}

// ---------------- block-reduce helper ----------------
__device__ __forceinline__ float warp_sum(float v) {
    #pragma unroll
    for (int o = 16; o; o >>= 1) v += __shfl_down_sync(0xffffffffu, v, o);
    return v;
}

// ---------------- LayerNorm (row length 768), 192 threads, float4 path ----------------
// t = x + r1 + r2 + r3 + r4 + colbias (any of r*/colbias may be null)
// out = LN(t)*g + b (fp32); optional fp16 copy oh.
template <int F16OUT>
__global__ __launch_bounds__(192)
void ln_kernel(const float* __restrict__ x,
               const float* __restrict__ rp1, const float* __restrict__ rp2,
               const float* __restrict__ rp3, const float* __restrict__ rp4,
               const float* __restrict__ colbias,
               const float* __restrict__ g, const float* __restrict__ b,
               float* __restrict__ out, __half* __restrict__ oh) {
    const int row = blockIdx.x;
    const int tid = threadIdx.x;            // 0..191
    const int c = tid * 4;
    const size_t off = (size_t)row * D_ + c;

    float4 t = *(const float4*)(x + off);
    if (rp1) { float4 r = *(const float4*)(rp1 + off); t.x += r.x; t.y += r.y; t.z += r.z; t.w += r.w; }
    if (rp2) { float4 r = *(const float4*)(rp2 + off); t.x += r.x; t.y += r.y; t.z += r.z; t.w += r.w; }
    if (rp3) { float4 r = *(const float4*)(rp3 + off); t.x += r.x; t.y += r.y; t.z += r.z; t.w += r.w; }
    if (rp4) { float4 r = *(const float4*)(rp4 + off); t.x += r.x; t.y += r.y; t.z += r.z; t.w += r.w; }
    if (colbias) { float4 r = *(const float4*)(colbias + c); t.x += r.x; t.y += r.y; t.z += r.z; t.w += r.w; }

    float s = t.x + t.y + t.z + t.w;
    float s2 = t.x * t.x + t.y * t.y + t.z * t.z + t.w * t.w;

    __shared__ float red[2][6];
    __shared__ float stat[2];
    int lane = tid & 31, wid = tid >> 5;
    s = warp_sum(s); s2 = warp_sum(s2);
    if (lane == 0) { red[0][wid] = s; red[1][wid] = s2; }
    __syncthreads();
    if (tid == 0) {
        float a = 0.f, cc = 0.f;
        #pragma unroll
        for (int i = 0; i < 6; i++) { a += red[0][i]; cc += red[1][i]; }
        float mean = a * (1.0f / D_);
        float var = cc * (1.0f / D_) - mean * mean;
        stat[0] = mean;
        stat[1] = rsqrtf(var + EPS_);
    }
    __syncthreads();
    const float mean = stat[0], inv = stat[1];

    float4 gg = *(const float4*)(g + c);
    float4 bb = *(const float4*)(b + c);
    float4 o;
    o.x = (t.x - mean) * inv * gg.x + bb.x;
    o.y = (t.y - mean) * inv * gg.y + bb.y;
    o.z = (t.z - mean) * inv * gg.z + bb.z;
    o.w = (t.w - mean) * inv * gg.w + bb.w;
    *(float4*)(out + off) = o;
    if (F16OUT) {
        __half2 h01 = __floats2half2_rn(o.x, o.y);
        __half2 h23 = __floats2half2_rn(o.z, o.w);
        uint2 pk = make_uint2(*(uint32_t*)&h01, *(uint32_t*)&h23);
        *(uint2*)(oh + off) = pk;
    }
}

// ---------------- param_bias (symmetric, runs once) ----------------
__global__ __launch_bounds__(256)
void pbias_kernel(const float* __restrict__ enc, float* __restrict__ pbias) {
    __shared__ float Es[112 * 97];
    const int b = blockIdx.x >> 3;
    const int h = blockIdx.x & 7;
    const int tid = threadIdx.x;
    const float* src = enc + (size_t)(b * S_) * D_ + h * HD_;

    for (int i = tid; i < 112 * 96; i += 256) {
        int s = i / 96, d = i - s * 96;
        Es[s * 97 + d] = (s < S_) ? src[(size_t)s * D_ + d] : 0.f;
    }
    __syncthreads();

    const int tx = tid & 15, ty = tid >> 4;
    float acc[7][7];
    #pragma unroll
    for (int ii = 0; ii < 7; ii++)
        #pragma unroll
        for (int jj = 0; jj < 7; jj++) acc[ii][jj] = 0.f;

    for (int d = 0; d < 96; d++) {
        float a[7], bb[7];
        #pragma unroll
        for (int ii = 0; ii < 7; ii++) a[ii]  = Es[(ty + 16 * ii) * 97 + d];
        #pragma unroll
        for (int jj = 0; jj < 7; jj++) bb[jj] = Es[(tx + 16 * jj) * 97 + d];
        #pragma unroll
        for (int ii = 0; ii < 7; ii++)
            #pragma unroll
            for (int jj = 0; jj < 7; jj++)
                if (jj >= ii) acc[ii][jj] += a[ii] * bb[jj];
    }

    float* dst = pbias + (size_t)blockIdx.x * (S_ * S_);
    #pragma unroll
    for (int ii = 0; ii < 7; ii++) {
        int i = ty + 16 * ii;
        if (i >= S_) continue;
        #pragma unroll
        for (int jj = 0; jj < 7; jj++) {
            if (jj < ii) continue;
            int j = tx + 16 * jj;
            if (j < S_) {
                float v = acc[ii][jj] * INV_SQRT_HD;
                dst[i * S_ + j] = v;
                if (jj > ii) dst[j * S_ + i] = v;
            }
        }
    }
}

// ---------------- fused attention on tensor cores ----------------
#define QSW 104
#define SSW 120
#define ATTN_SMEM (112 * QSW * 2 + 112 * SSW * 2)   // 50176
__global__ __launch_bounds__(256, 3)
void attn_kernel(const __half* __restrict__ xq, const float* __restrict__ pbias,
                 float* __restrict__ out) {
    extern __shared__ char asm_[];
    __half* Qh = (__half*)asm_;
    __half* Ss = Qh + 112 * QSW;
    const uint32_t qb = smem_u32(Qh);
    const uint32_t sbS = smem_u32(Ss);

    const int b = blockIdx.x >> 3;
    const int h = blockIdx.x & 7;
    const int tid = threadIdx.x;
    const int wid = tid >> 5, lane = tid & 31;

    const __half* src = xq + (size_t)(b * S_) * D_ + h * HD_;
    for (int i = tid; i < 112 * 12; i += 256) {
        int s = i / 12, c = i % 12;
        uint4 v = make_uint4(0u, 0u, 0u, 0u);
        if (s < S_) v = *(const uint4*)(src + (size_t)s * D_ + c * 8);
        *(uint4*)(Qh + s * QSW + c * 8) = v;
    }
    __syncthreads();

    // ---- matmul1: scores ----
    if (wid < 7) {
        float acc[14][4];
        #pragma unroll
        for (int i = 0; i < 14; i++)
            #pragma unroll
            for (int k = 0; k < 4; k++) acc[i][k] = 0.f;

        const uint32_t aoff = qb + (uint32_t)((wid * 16 + (lane & 15)) * 208 + (lane >> 4) * 16);
        const uint32_t boff = qb + (uint32_t)((((lane >> 4) << 3) + (lane & 7)) * 208
                                              + ((lane >> 3) & 1) * 16);
        #pragma unroll
        for (int k = 0; k < 6; k++) {
            uint32_t a[4];
            LDSM4(a, aoff + k * 32);
            #pragma unroll
            for (int p = 0; p < 7; p++) {
                uint32_t t[4];
                LDSM4(t, boff + (uint32_t)(p * 16 * 208) + k * 32);
                uint32_t b0[2] = {t[0], t[1]}, b1[2] = {t[2], t[3]};
                MMA_F16(acc[2 * p], a, b0);
                MMA_F16(acc[2 * p + 1], a, b1);
            }
        }
        const float* pb = pbias + (size_t)blockIdx.x * (S_ * S_);
        const int r = lane >> 2, c0 = (lane & 3) * 2;
        const int i0 = wid * 16 + r, i1 = i0 + 8;
        #pragma unroll
        for (int nf = 0; nf < 14; nf++) {
            int j = nf * 8 + c0;
            float p00 = (i0 < S_ && j < S_)     ? pb[i0 * S_ + j]     : 0.f;
            float p01 = (i0 < S_ && j + 1 < S_) ? pb[i0 * S_ + j + 1] : 0.f;
            float p10 = (i1 < S_ && j < S_)     ? pb[i1 * S_ + j]     : 0.f;
            float p11 = (i1 < S_ && j + 1 < S_) ? pb[i1 * S_ + j + 1] : 0.f;
            Ss[i0 * SSW + j]     = __float2half(acc[nf][0] * INV_SQRT_HD + p00);
            Ss[i0 * SSW + j + 1] = __float2half(acc[nf][1] * INV_SQRT_HD + p01);
            Ss[i1 * SSW + j]     = __float2half(acc[nf][2] * INV_SQRT_HD + p10);
            Ss[i1 * SSW + j + 1] = __float2half(acc[nf][3] * INV_SQRT_HD + p11);
        }
    }
    __syncthreads();

    // ---- softmax rows (threads 0..99) ----
    if (tid < S_) {
        __half* row = Ss + tid * SSW;
        float m = -1e30f;
        for (int j = 0; j < S_; j++) m = fmaxf(m, __half2float(row[j]));
        float sum = 0.f;
        for (int j = 0; j < S_; j++) {
            float e = expf(__half2float(row[j]) - m);
            row[j] = __float2half(e);
            sum += e;
        }
        float inv = 1.0f / sum;
        for (int j = 0; j < S_; j++)
            row[j] = __float2half(__half2float(row[j]) * inv);
        for (int j = S_; j < 112; j++) row[j] = __float2half(0.f);
    }
    __syncthreads();

    // ---- matmul2: out = P Q ----
    if (wid < 7) {
        float acc[12][4];
        #pragma unroll
        for (int i = 0; i < 12; i++)
            #pragma unroll
            for (int k = 0; k < 4; k++) acc[i][k] = 0.f;

        const uint32_t aoff = sbS + (uint32_t)((wid * 16 + (lane & 15)) * 240 + (lane >> 4) * 16);
        const uint32_t btr = qb + (uint32_t)((((lane >> 3) & 1) * 8 + (lane & 7)) * 208
                                             + ((lane >> 4) * 8) * 2);
        #pragma unroll
        for (int k = 0; k < 7; k++) {
            uint32_t a[4];
            LDSM4(a, aoff + k * 32);
            #pragma unroll
            for (int p = 0; p < 6; p++) {
                uint32_t t[4];
                LDSM4T(t, btr + (uint32_t)(k * 16 * 208) + (uint32_t)(p * 32));
                uint32_t b0[2] = {t[0], t[1]}, b1[2] = {t[2], t[3]};
                MMA_F16(acc[2 * p], a, b0);
                MMA_F16(acc[2 * p + 1], a, b1);
            }
        }
        float* dst = out + (size_t)(b * S_) * D_ + h * HD_;
        const int r = lane >> 2, c0 = (lane & 3) * 2;
        const int i0 = wid * 16 + r, i1 = i0 + 8;
        #pragma unroll
        for (int nf = 0; nf < 12; nf++) {
            int d = nf * 8 + c0;
            if (i0 < S_) {
                dst[(size_t)i0 * D_ + d]     = acc[nf][0];
                dst[(size_t)i0 * D_ + d + 1] = acc[nf][1];
            }
            if (i1 < S_) {
                dst[(size_t)i1 * D_ + d]     = acc[nf][2];
                dst[(size_t)i1 * D_ + d + 1] = acc[nf][3];
            }
        }
    }
}

// ---------------- final classifier ----------------
__global__ void fc_kernel(const float* __restrict__ x, const float* __restrict__ Wfc,
                          const float* __restrict__ bfc, float* __restrict__ out) {
    const int b = blockIdx.x;
    const int tid = threadIdx.x;
    const float* xr = x + (size_t)b * (S_ * D_);
    float a0 = 0.f, a1 = 0.f;
    for (int i = tid; i < S_ * D_; i += 256) {
        float v = xr[i];
        a0 += v * Wfc[2 * i];
        a1 += v * Wfc[2 * i + 1];
    }
    __shared__ float red[2][8];
    int lane = tid & 31, wid = tid >> 5;
    a0 = warp_sum(a0); a1 = warp_sum(a1);
    if (lane == 0) { red[0][wid] = a0; red[1][wid] = a1; }
    __syncthreads();
    if (wid == 0) {
        float r0 = (lane < 8) ? red[0][lane] : 0.f;
        float r1 = (lane < 8) ? red[1][lane] : 0.f;
        r0 = warp_sum(r0); r1 = warp_sum(r1);
        if (lane == 0) {
            out[2 * b + 0] = r0 + bfc[0];
            out[2 * b + 1] = r1 + bfc[1];
        }
    }
}

// ---------------- launch ----------------
extern "C" void kernel_launch(void* const* d_in, const int* in_sizes, int n_in,
                              void* d_out, int out_size) {
    const float* tseq = (const float*)d_in[0];
    const float* pseq = (const float*)d_in[1];
    const float* Wc  = (const float*)d_in[2];
    const float* bc  = (const float*)d_in[3];
    const float* gp  = (const float*)d_in[4];
    const float* bp  = (const float*)d_in[5];
    const float* W1  = (const float*)d_in[6];
    const float* b1  = (const float*)d_in[7];
    const float* W2  = (const float*)d_in[8];
    const float* b2  = (const float*)d_in[9];
    const float* g1  = (const float*)d_in[10];
    const float* bn1 = (const float*)d_in[11];
    const float* g2  = (const float*)d_in[12];
    const float* bn2 = (const float*)d_in[13];
    const float* Wfc = (const float*)d_in[14];
    const float* bfc = (const float*)d_in[15];
    float* out = (float*)d_out;

    float *x, *enc, *pbias, *part, *pe;
    __half *xq, *xhi, *phi, *plo, *ffhi;
    __half *w1h, *w2h, *wch;
    cudaGetSymbolAddress((void**)&x, g_x);
    cudaGetSymbolAddress((void**)&enc, g_enc);
    cudaGetSymbolAddress((void**)&pbias, g_pbias);
    cudaGetSymbolAddress((void**)&part, g_part);
    cudaGetSymbolAddress((void**)&pe, g_pe);
    cudaGetSymbolAddress((void**)&xq, g_xq);
    cudaGetSymbolAddress((void**)&xhi, g_xhi);
    cudaGetSymbolAddress((void**)&phi, g_phi);
    cudaGetSymbolAddress((void**)&plo, g_plo);
    cudaGetSymbolAddress((void**)&ffhi, g_ffhi);
    cudaGetSymbolAddress((void**)&w1h, g_w1h);
    cudaGetSymbolAddress((void**)&w2h, g_w2h);
    cudaGetSymbolAddress((void**)&wch, g_wch);
    float* part0 = part;
    float* part1 = part + (size_t)M_ * D_;
    float* part2 = part + (size_t)2 * M_ * D_;
    float* part3 = part + (size_t)3 * M_ * D_;

    cudaFuncSetAttribute(attn_kernel, cudaFuncAttributeMaxDynamicSharedMemorySize, ATTN_SMEM);
    cudaFuncSetAttribute((mma_gemm<1, 0, 64>), cudaFuncAttributeMaxDynamicSharedMemorySize, GEMM_SMEM_T0_64);
    cudaFuncSetAttribute((mma_gemm<2, 0, 64>), cudaFuncAttributeMaxDynamicSharedMemorySize, GEMM_SMEM_T0_64);
    cudaFuncSetAttribute((mma_gemm<2, 1, 32>), cudaFuncAttributeMaxDynamicSharedMemorySize, GEMM_SMEM_T1_32);

    // weight transpose + fp16 convert (tiny, one-time per launch)
    wconv_kernel<<<dim3(D_ / 32, FF_ / 32), dim3(32, 8)>>>(W1, w1h, D_, FF_);
    wconv_kernel<<<dim3(FF_ / 32, D_ / 32), dim3(32, 8)>>>(W2, w2h, FF_, D_);
    wconv_kernel<<<dim3(D_ / 32, D_ / 32),  dim3(32, 8)>>>(Wc, wch, D_, D_);

    const int total = M_ * D_;
    pe_kernel<<<(S_ * D_ + 255) / 256, 256>>>(pe);
    add_pe_kernel<<<(total + 255) / 256, 256>>>(tseq, pe, x, xq);
    pool_kernel<<<(total + 255) / 256, 256>>>(pseq, phi, plo);

    // param encoder: enc = LN(pooled @ Wc + bc)  (split-K=2, exact 2-term A)
    mma_gemm<2, 1, 32><<<dim3(D_ / BNT, M_ / BMT, 2), 256, GEMM_SMEM_T1_32>>>(
        phi, plo, wch, nullptr, part0, nullptr, M_, D_, D_);
    ln_kernel<0><<<M_, 192>>>(part0, part1, nullptr, nullptr, nullptr, bc, gp, bp, enc, nullptr);

    // layer-invariant attention bias
    pbias_kernel<<<B_ * H_, 256>>>(enc, pbias);

    for (int l = 0; l < NLAYERS; l++) {
        attn_kernel<<<B_ * H_, 256, ATTN_SMEM>>>(xq, pbias, part0);
        ln_kernel<1><<<M_, 192>>>(x, part0, nullptr, nullptr, nullptr, nullptr, g1, bn1, x, xhi);
        // FFN1: single-fp16 A, gelu -> single fp16 ff   (BKS=64)
        mma_gemm<1, 0, 64><<<dim3(FF_ / BNT, M_ / BMT), 256, GEMM_SMEM_T0_64>>>(
            xhi, nullptr, w1h, b1, nullptr, ffhi, M_, FF_, D_);
        // FFN2: single-fp16 A, split-K=4 -> four fp32 partials, b2 folded into LN
        mma_gemm<2, 0, 64><<<dim3(D_ / BNT, M_ / BMT, 4), 256, GEMM_SMEM_T0_64>>>(
            ffhi, nullptr, w2h, nullptr, part0, nullptr, M_, D_, FF_);
        // end-of-layer LN: x + 4 partials + b2; fp32 x + fp16 copy for next attn
        ln_kernel<1><<<M_, 192>>>(x, part0, part1, part2, part3, b2, g2, bn2, x, xq);
    }

    fc_kernel<<<B_, 256>>>(x, Wfc, bfc, out);
}

// round 14
// speedup vs baseline: 1.0357x; 1.0357x over previous
#include <cuda_runtime.h>
#include <cuda_fp16.h>
#include <math.h>
#include <stdint.h>

// ---------------- problem constants ----------------
#define B_   64
#define S_   100
#define D_   768
#define H_   8
#define HD_  96
#define P_   8
#define FF_  3072
#define M_   (B_ * S_)            // 6400 rows
#define NLAYERS 4
#define EPS_ 1e-5f
#define INV_SQRT_HD 0.10206207261596575f   // 1/sqrt(96)

// ---------------- device scratch ----------------
__device__ float g_x[M_ * D_];
__device__ float g_enc[M_ * D_];
__device__ float g_pbias[B_ * H_ * S_ * S_];
__device__ float g_part[2][M_ * D_];   // split-K fp32 partials
__device__ float g_pe[S_ * D_];

__device__ __half g_xq[M_ * D_];     // fp16 of attn input (layer input)
__device__ __half g_xhi[M_ * D_];    // fp16 of LN1 output (FFN1 input)
__device__ __half g_phi[M_ * D_];
__device__ __half g_plo[M_ * D_];
__device__ __half g_ffhi[(size_t)M_ * FF_];
__device__ __half g_w1h[(size_t)FF_ * D_];   // [N=3072][K=768] fp16
__device__ __half g_w2h[(size_t)D_ * FF_];   // [N=768][K=3072] fp16
__device__ __half g_wch[(size_t)D_ * D_];    // [N=768][K=768]  fp16

// ============================================================
// PTX helpers (mma.sync / ldmatrix / cp.async — all baseline sm_80+)
// ============================================================
__device__ __forceinline__ uint32_t smem_u32(const void* p) {
    uint32_t a;
    asm("{ .reg .u64 t; cvta.to.shared.u64 t, %1; cvt.u32.u64 %0, t; }" : "=r"(a) : "l"(p));
    return a;
}

#define CP_ASYNC16(dst, src) \
    asm volatile("cp.async.cg.shared.global [%0], [%1], 16;\n" :: "r"(dst), "l"(src) : "memory")
#define CP_COMMIT() asm volatile("cp.async.commit_group;\n" ::: "memory")
#define CP_WAIT0()  asm volatile("cp.async.wait_group 0;\n" ::: "memory")
#define CP_WAIT1()  asm volatile("cp.async.wait_group 1;\n" ::: "memory")

#define LDSM4(r, addr) \
    asm volatile("ldmatrix.sync.aligned.m8n8.x4.shared.b16 {%0,%1,%2,%3}, [%4];" \
        : "=r"((r)[0]), "=r"((r)[1]), "=r"((r)[2]), "=r"((r)[3]) : "r"(addr))

#define LDSM4T(r, addr) \
    asm volatile("ldmatrix.sync.aligned.m8n8.x4.trans.shared.b16 {%0,%1,%2,%3}, [%4];" \
        : "=r"((r)[0]), "=r"((r)[1]), "=r"((r)[2]), "=r"((r)[3]) : "r"(addr))

#define MMA_F16(c, a, b) \
    asm volatile("mma.sync.aligned.m16n8k16.row.col.f32.f16.f16.f32 " \
        "{%0,%1,%2,%3}, {%4,%5,%6,%7}, {%8,%9}, {%0,%1,%2,%3};" \
        : "+f"((c)[0]), "+f"((c)[1]), "+f"((c)[2]), "+f"((c)[3]) \
        : "r"((a)[0]), "r"((a)[1]), "r"((a)[2]), "r"((a)[3]), "r"((b)[0]), "r"((b)[1]))

__device__ __forceinline__ float gelu_exact(float v) {
    return 0.5f * v * (1.0f + erff(v * 0.70710678118654752f));
}
__device__ __forceinline__ void split_f16(float v, __half& h, __half& l) {
    h = __float2half(v);
    l = __float2half(v - __half2float(h));
}

// ============================================================
// GEMM: C[M,N] = A[M,K] @ B^T[N,K] (+ bias)
// TT=1: A = Ah + Al (fp16 pair); TT=0: A = Ah single fp16. B single fp16.
// EPI 1: bias + gelu -> single fp16 out. EPI 2: fp32 partial, z-indexed.
// BKS templated. 3-stage cp.async ring, 2 CTAs/SM.
// ============================================================
#define BMT 128
#define BNT 128
#define NSTAGE 3

template <int BKSv> struct GP {
    static constexpr uint32_t ROWB = BKSv * 2 + 16;
    static constexpr uint32_t MATB = 128u * ROWB;
};
#define GEMM_SMEM_T1_32 (NSTAGE * 3 * GP<32>::MATB)       // 92160 (encoder)
#define GEMM_SMEM_T0_64 (NSTAGE * 2 * GP<64>::MATB)       // 110592 (FFN)

template <int EPI, int TT, int BKSv>
__global__ __launch_bounds__(256, 2)
void mma_gemm(const __half* __restrict__ Ah_, const __half* __restrict__ Al_,
              const __half* __restrict__ Bh_,
              const float* __restrict__ bias,
              float* __restrict__ Cf, __half* __restrict__ Ch,
              int M, int N, int K)
{
    constexpr uint32_t ROWB = GP<BKSv>::ROWB;
    constexpr uint32_t MATB = GP<BKSv>::MATB;
    constexpr int NMAT = TT ? 3 : 2;
    constexpr uint32_t BUFB = NMAT * MATB;
    constexpr int CHUNKS_PER_MAT = 128 * (BKSv / 8);
    constexpr int LOAD_ITERS = NMAT * CHUNKS_PER_MAT / 256;
    constexpr int KHN = BKSv / 16;

    extern __shared__ char dsm[];
    const uint32_t sb0 = smem_u32(dsm);
    const int tid = threadIdx.x;
    const int wid = tid >> 5, lane = tid & 31;
    const int wm = wid >> 1, wn = wid & 1;
    const int row0 = blockIdx.y * BMT, col0 = blockIdx.x * BNT;
    const int Kloc = K / gridDim.z;
    const int koff = blockIdx.z * Kloc;
    const int NS = Kloc / BKSv;

    const __half* Ahp = Ah_ + koff;
    const __half* Alp = TT ? Al_ + koff : nullptr;
    const __half* Bhp = Bh_ + koff;

    float acc[2][8][4];
    #pragma unroll
    for (int i = 0; i < 2; i++)
        #pragma unroll
        for (int j = 0; j < 8; j++)
            #pragma unroll
            for (int k = 0; k < 4; k++) acc[i][j][k] = 0.f;

    const uint32_t aoff = (uint32_t)(wm * 32 + (lane & 15)) * ROWB + (uint32_t)(lane >> 4) * 16;
    const uint32_t boff = (uint32_t)(wn * 64 + ((lane >> 4) << 3) + (lane & 7)) * ROWB
                        + (uint32_t)((lane >> 3) & 1) * 16;
    const uint32_t BOFFM = (TT ? 2u : 1u) * MATB;

    auto load_step = [&](int s) {
        const uint32_t sb = sb0 + (uint32_t)(s % NSTAGE) * BUFB;
        const int k0 = s * BKSv;
        #pragma unroll
        for (int i = 0; i < LOAD_ITERS; i++) {
            int u = i * 256 + tid;
            int mat = u / CHUNKS_PER_MAT;
            int v = u % CHUNKS_PER_MAT;
            int r = v / (BKSv / 8), c = v % (BKSv / 8);
            const __half* src;
            if (TT) {
                if (mat == 0)      src = Ahp + (size_t)(row0 + r) * K + k0 + c * 8;
                else if (mat == 1) src = Alp + (size_t)(row0 + r) * K + k0 + c * 8;
                else               src = Bhp + (size_t)(col0 + r) * K + k0 + c * 8;
            } else {
                if (mat == 0)      src = Ahp + (size_t)(row0 + r) * K + k0 + c * 8;
                else               src = Bhp + (size_t)(col0 + r) * K + k0 + c * 8;
            }
            CP_ASYNC16(sb + (uint32_t)mat * MATB + (uint32_t)r * ROWB + (uint32_t)c * 16, src);
        }
        CP_COMMIT();
    };

    load_step(0);
    if (NS > 1) load_step(1);

    for (int s = 0; s < NS; s++) {
        if (s < NS - 1) { CP_WAIT1(); } else { CP_WAIT0(); }
        __syncthreads();
        if (s + 2 < NS) load_step(s + 2);

        const uint32_t sb = sb0 + (uint32_t)(s % NSTAGE) * BUFB;
        #pragma unroll
        for (int kh = 0; kh < KHN; kh++) {
            uint32_t ah[2][4], al[2][4], b[8][2];
            #pragma unroll
            for (int mf = 0; mf < 2; mf++) {
                LDSM4(ah[mf], sb + aoff + (uint32_t)(mf * 16) * ROWB + (uint32_t)kh * 32);
                if (TT) LDSM4(al[mf], sb + MATB + aoff + (uint32_t)(mf * 16) * ROWB + (uint32_t)kh * 32);
            }
            #pragma unroll
            for (int p = 0; p < 4; p++) {
                uint32_t t[4];
                LDSM4(t, sb + BOFFM + boff + (uint32_t)(p * 16) * ROWB + (uint32_t)kh * 32);
                b[2 * p][0] = t[0]; b[2 * p][1] = t[1];
                b[2 * p + 1][0] = t[2]; b[2 * p + 1][1] = t[3];
            }
            #pragma unroll
            for (int mf = 0; mf < 2; mf++)
                #pragma unroll
                for (int nf = 0; nf < 8; nf++) {
                    MMA_F16(acc[mf][nf], ah[mf], b[nf]);
                    if (TT) MMA_F16(acc[mf][nf], al[mf], b[nf]);
                }
        }
    }

    // ---- epilogue ----
    __syncthreads();
    float* stg = (float*)dsm + wid * (16 * 65);
    const int gcol0 = col0 + wn * 64;
    const float bv0 = (EPI == 2) ? 0.f : bias[gcol0 + lane];
    const float bv1 = (EPI == 2) ? 0.f : bias[gcol0 + 32 + lane];
    const int r1 = lane >> 2, c0 = (lane & 3) * 2;
    float* Cfz = (EPI == 2) ? Cf + (size_t)blockIdx.z * M * N : Cf;

    #pragma unroll
    for (int mf = 0; mf < 2; mf++) {
        #pragma unroll
        for (int nf = 0; nf < 8; nf++) {
            stg[r1 * 65 + nf * 8 + c0]           = acc[mf][nf][0];
            stg[r1 * 65 + nf * 8 + c0 + 1]       = acc[mf][nf][1];
            stg[(r1 + 8) * 65 + nf * 8 + c0]     = acc[mf][nf][2];
            stg[(r1 + 8) * 65 + nf * 8 + c0 + 1] = acc[mf][nf][3];
        }
        __syncwarp();
        const int grow = row0 + wm * 32 + mf * 16;
        #pragma unroll
        for (int r = 0; r < 16; r++) {
            float v0 = stg[r * 65 + lane] + bv0;
            float v1 = stg[r * 65 + 32 + lane] + bv1;
            if (EPI == 1) {
                v0 = gelu_exact(v0);
                v1 = gelu_exact(v1);
                size_t base = (size_t)(grow + r) * N + gcol0;
                Ch[base + lane] = __float2half(v0);
                Ch[base + 32 + lane] = __float2half(v1);
            } else {
                size_t base = (size_t)(grow + r) * N + gcol0;
                Cfz[base + lane] = v0;
                Cfz[base + 32 + lane] = v1;
            }
        }
        __syncwarp();
    }
}

// ============================================================
// weight transpose + fp16 convert
// ============================================================
__global__ void wconv_kernel(const float* __restrict__ W, __half* __restrict__ Th,
                             int K, int N) {
    __shared__ float t[32][33];
    int k0 = blockIdx.x * 32, n0 = blockIdx.y * 32;
    int tx = threadIdx.x, ty = threadIdx.y;
    #pragma unroll
    for (int i = 0; i < 4; i++)
        t[ty + i * 8][tx] = W[(size_t)(k0 + ty + i * 8) * N + n0 + tx];
    __syncthreads();
    #pragma unroll
    for (int i = 0; i < 4; i++) {
        int n = n0 + ty + i * 8, k = k0 + tx;
        Th[(size_t)n * K + k] = __float2half(t[tx][ty + i * 8]);
    }
}

// ---------------- positional-encoding table ----------------
__global__ void pe_kernel(float* __restrict__ pe) {
    int idx = blockIdx.x * 256 + threadIdx.x;
    if (idx >= S_ * D_) return;
    int d = idx % D_;
    int s = idx / D_;
    int i2 = d & ~1;
    float div = expf((float)i2 * (-9.210340371976184f / (float)D_));
    float ang = (float)s * div;
    pe[idx] = (d & 1) ? cosf(ang) : sinf(ang);
}

// ---------------- x = template + pe; also emit fp16 copy ----------------
__global__ void add_pe_kernel(const float* __restrict__ t, const float* __restrict__ pe,
                              float* __restrict__ x, __half* __restrict__ xq) {
    int idx = blockIdx.x * 256 + threadIdx.x;
    if (idx >= M_ * D_) return;
    float v = t[idx] + pe[idx % (S_ * D_)];
    x[idx] = v;
    xq[idx] = __float2half(v);
}

// ---------------- pooled = mean over P, emitted as fp16 hi/lo ----------------
__global__ void pool_kernel(const float* __restrict__ ps,
                            __half* __restrict__ ph, __half* __restrict__ pl) {
    int idx = blockIdx.x * 256 + threadIdx.x;
    if (idx >= M_ * D_) return;
    int bs = idx / D_;
    int c  = idx % D_;
    const float* base = ps + (size_t)bs * (P_ * D_) + c;
    float s = 0.f;
    #pragma unroll
    for (int p = 0; p < P_; p++) s += base[p * D_];
    float m = s * (1.0f / P_);
    __half h, l;
    split_f16(m, h, l);
    ph[idx] = h; pl[idx] = l;
}

// ---------------- block-reduce helper ----------------
__device__ __forceinline__ float warp_sum(float v) {
    #pragma unroll
    for (int o = 16; o; o >>= 1) v += __shfl_down_sync(0xffffffffu, v, o);
    return v;
}

// ---------------- LayerNorm (row length 768), 192 threads, float4 path ----------------
// t = x + r1 + r2 + colbias (any may be null); out = LN(t)*g + b; optional fp16 oh.
template <int F16OUT>
__global__ __launch_bounds__(192)
void ln_kernel(const float* __restrict__ x,
               const float* __restrict__ rp1, const float* __restrict__ rp2,
               const float* __restrict__ colbias,
               const float* __restrict__ g, const float* __restrict__ b,
               float* __restrict__ out, __half* __restrict__ oh) {
    const int row = blockIdx.x;
    const int tid = threadIdx.x;            // 0..191
    const int c = tid * 4;
    const size_t off = (size_t)row * D_ + c;

    float4 t = *(const float4*)(x + off);
    if (rp1) { float4 r = *(const float4*)(rp1 + off); t.x += r.x; t.y += r.y; t.z += r.z; t.w += r.w; }
    if (rp2) { float4 r = *(const float4*)(rp2 + off); t.x += r.x; t.y += r.y; t.z += r.z; t.w += r.w; }
    if (colbias) { float4 r = *(const float4*)(colbias + c); t.x += r.x; t.y += r.y; t.z += r.z; t.w += r.w; }

    float s = t.x + t.y + t.z + t.w;
    float s2 = t.x * t.x + t.y * t.y + t.z * t.z + t.w * t.w;

    __shared__ float red[2][6];
    __shared__ float stat[2];
    int lane = tid & 31, wid = tid >> 5;
    s = warp_sum(s); s2 = warp_sum(s2);
    if (lane == 0) { red[0][wid] = s; red[1][wid] = s2; }
    __syncthreads();
    if (tid == 0) {
        float a = 0.f, cc = 0.f;
        #pragma unroll
        for (int i = 0; i < 6; i++) { a += red[0][i]; cc += red[1][i]; }
        float mean = a * (1.0f / D_);
        float var = cc * (1.0f / D_) - mean * mean;
        stat[0] = mean;
        stat[1] = rsqrtf(var + EPS_);
    }
    __syncthreads();
    const float mean = stat[0], inv = stat[1];

    float4 gg = *(const float4*)(g + c);
    float4 bb = *(const float4*)(b + c);
    float4 o;
    o.x = (t.x - mean) * inv * gg.x + bb.x;
    o.y = (t.y - mean) * inv * gg.y + bb.y;
    o.z = (t.z - mean) * inv * gg.z + bb.z;
    o.w = (t.w - mean) * inv * gg.w + bb.w;
    *(float4*)(out + off) = o;
    if (F16OUT) {
        __half2 h01 = __floats2half2_rn(o.x, o.y);
        __half2 h23 = __floats2half2_rn(o.z, o.w);
        uint2 pk = make_uint2(*(uint32_t*)&h01, *(uint32_t*)&h23);
        *(uint2*)(oh + off) = pk;
    }
}

// ---------------- param_bias (symmetric, runs once) ----------------
__global__ __launch_bounds__(256)
void pbias_kernel(const float* __restrict__ enc, float* __restrict__ pbias) {
    __shared__ float Es[112 * 97];
    const int b = blockIdx.x >> 3;
    const int h = blockIdx.x & 7;
    const int tid = threadIdx.x;
    const float* src = enc + (size_t)(b * S_) * D_ + h * HD_;

    for (int i = tid; i < 112 * 96; i += 256) {
        int s = i / 96, d = i - s * 96;
        Es[s * 97 + d] = (s < S_) ? src[(size_t)s * D_ + d] : 0.f;
    }
    __syncthreads();

    const int tx = tid & 15, ty = tid >> 4;
    float acc[7][7];
    #pragma unroll
    for (int ii = 0; ii < 7; ii++)
        #pragma unroll
        for (int jj = 0; jj < 7; jj++) acc[ii][jj] = 0.f;

    for (int d = 0; d < 96; d++) {
        float a[7], bb[7];
        #pragma unroll
        for (int ii = 0; ii < 7; ii++) a[ii]  = Es[(ty + 16 * ii) * 97 + d];
        #pragma unroll
        for (int jj = 0; jj < 7; jj++) bb[jj] = Es[(tx + 16 * jj) * 97 + d];
        #pragma unroll
        for (int ii = 0; ii < 7; ii++)
            #pragma unroll
            for (int jj = 0; jj < 7; jj++)
                if (jj >= ii) acc[ii][jj] += a[ii] * bb[jj];
    }

    float* dst = pbias + (size_t)blockIdx.x * (S_ * S_);
    #pragma unroll
    for (int ii = 0; ii < 7; ii++) {
        int i = ty + 16 * ii;
        if (i >= S_) continue;
        #pragma unroll
        for (int jj = 0; jj < 7; jj++) {
            if (jj < ii) continue;
            int j = tx + 16 * jj;
            if (j < S_) {
                float v = acc[ii][jj] * INV_SQRT_HD;
                dst[i * S_ + j] = v;
                if (jj > ii) dst[j * S_ + i] = v;
            }
        }
    }
}

// ---------------- fused attention on tensor cores ----------------
#define QSW 104
#define SSW 120
#define ATTN_SMEM (112 * QSW * 2 + 112 * SSW * 2)   // 50176
__global__ __launch_bounds__(256, 3)
void attn_kernel(const __half* __restrict__ xq, const float* __restrict__ pbias,
                 float* __restrict__ out) {
    extern __shared__ char asm_[];
    __half* Qh = (__half*)asm_;
    __half* Ss = Qh + 112 * QSW;
    const uint32_t qb = smem_u32(Qh);
    const uint32_t sbS = smem_u32(Ss);

    const int b = blockIdx.x >> 3;
    const int h = blockIdx.x & 7;
    const int tid = threadIdx.x;
    const int wid = tid >> 5, lane = tid & 31;

    const __half* src = xq + (size_t)(b * S_) * D_ + h * HD_;
    for (int i = tid; i < 112 * 12; i += 256) {
        int s = i / 12, c = i % 12;
        uint4 v = make_uint4(0u, 0u, 0u, 0u);
        if (s < S_) v = *(const uint4*)(src + (size_t)s * D_ + c * 8);
        *(uint4*)(Qh + s * QSW + c * 8) = v;
    }
    __syncthreads();

    // ---- matmul1: scores ----
    if (wid < 7) {
        float acc[14][4];
        #pragma unroll
        for (int i = 0; i < 14; i++)
            #pragma unroll
            for (int k = 0; k < 4; k++) acc[i][k] = 0.f;

        const uint32_t aoff = qb + (uint32_t)((wid * 16 + (lane & 15)) * 208 + (lane >> 4) * 16);
        const uint32_t boff = qb + (uint32_t)((((lane >> 4) << 3) + (lane & 7)) * 208
                                              + ((lane >> 3) & 1) * 16);
        #pragma unroll
        for (int k = 0; k < 6; k++) {
            uint32_t a[4];
            LDSM4(a, aoff + k * 32);
            #pragma unroll
            for (int p = 0; p < 7; p++) {
                uint32_t t[4];
                LDSM4(t, boff + (uint32_t)(p * 16 * 208) + k * 32);
                uint32_t b0[2] = {t[0], t[1]}, b1[2] = {t[2], t[3]};
                MMA_F16(acc[2 * p], a, b0);
                MMA_F16(acc[2 * p + 1], a, b1);
            }
        }
        const float* pb = pbias + (size_t)blockIdx.x * (S_ * S_);
        const int r = lane >> 2, c0 = (lane & 3) * 2;
        const int i0 = wid * 16 + r, i1 = i0 + 8;
        #pragma unroll
        for (int nf = 0; nf < 14; nf++) {
            int j = nf * 8 + c0;
            float p00 = (i0 < S_ && j < S_)     ? pb[i0 * S_ + j]     : 0.f;
            float p01 = (i0 < S_ && j + 1 < S_) ? pb[i0 * S_ + j + 1] : 0.f;
            float p10 = (i1 < S_ && j < S_)     ? pb[i1 * S_ + j]     : 0.f;
            float p11 = (i1 < S_ && j + 1 < S_) ? pb[i1 * S_ + j + 1] : 0.f;
            Ss[i0 * SSW + j]     = __float2half(acc[nf][0] * INV_SQRT_HD + p00);
            Ss[i0 * SSW + j + 1] = __float2half(acc[nf][1] * INV_SQRT_HD + p01);
            Ss[i1 * SSW + j]     = __float2half(acc[nf][2] * INV_SQRT_HD + p10);
            Ss[i1 * SSW + j + 1] = __float2half(acc[nf][3] * INV_SQRT_HD + p11);
        }
    }
    __syncthreads();

    // ---- softmax rows (threads 0..99) ----
    if (tid < S_) {
        __half* row = Ss + tid * SSW;
        float m = -1e30f;
        for (int j = 0; j < S_; j++) m = fmaxf(m, __half2float(row[j]));
        float sum = 0.f;
        for (int j = 0; j < S_; j++) {
            float e = expf(__half2float(row[j]) - m);
            row[j] = __float2half(e);
            sum += e;
        }
        float inv = 1.0f / sum;
        for (int j = 0; j < S_; j++)
            row[j] = __float2half(__half2float(row[j]) * inv);
        for (int j = S_; j < 112; j++) row[j] = __float2half(0.f);
    }
    __syncthreads();

    // ---- matmul2: out = P Q ----
    if (wid < 7) {
        float acc[12][4];
        #pragma unroll
        for (int i = 0; i < 12; i++)
            #pragma unroll
            for (int k = 0; k < 4; k++) acc[i][k] = 0.f;

        const uint32_t aoff = sbS + (uint32_t)((wid * 16 + (lane & 15)) * 240 + (lane >> 4) * 16);
        const uint32_t btr = qb + (uint32_t)((((lane >> 3) & 1) * 8 + (lane & 7)) * 208
                                             + ((lane >> 4) * 8) * 2);
        #pragma unroll
        for (int k = 0; k < 7; k++) {
            uint32_t a[4];
            LDSM4(a, aoff + k * 32);
            #pragma unroll
            for (int p = 0; p < 6; p++) {
                uint32_t t[4];
                LDSM4T(t, btr + (uint32_t)(k * 16 * 208) + (uint32_t)(p * 32));
                uint32_t b0[2] = {t[0], t[1]}, b1[2] = {t[2], t[3]};
                MMA_F16(acc[2 * p], a, b0);
                MMA_F16(acc[2 * p + 1], a, b1);
            }
        }
        float* dst = out + (size_t)(b * S_) * D_ + h * HD_;
        const int r = lane >> 2, c0 = (lane & 3) * 2;
        const int i0 = wid * 16 + r, i1 = i0 + 8;
        #pragma unroll
        for (int nf = 0; nf < 12; nf++) {
            int d = nf * 8 + c0;
            if (i0 < S_) {
                dst[(size_t)i0 * D_ + d]     = acc[nf][0];
                dst[(size_t)i0 * D_ + d + 1] = acc[nf][1];
            }
            if (i1 < S_) {
                dst[(size_t)i1 * D_ + d]     = acc[nf][2];
                dst[(size_t)i1 * D_ + d + 1] = acc[nf][3];
            }
        }
    }
}

// ---------------- final classifier ----------------
__global__ void fc_kernel(const float* __restrict__ x, const float* __restrict__ Wfc,
                          const float* __restrict__ bfc, float* __restrict__ out) {
    const int b = blockIdx.x;
    const int tid = threadIdx.x;
    const float* xr = x + (size_t)b * (S_ * D_);
    float a0 = 0.f, a1 = 0.f;
    for (int i = tid; i < S_ * D_; i += 256) {
        float v = xr[i];
        a0 += v * Wfc[2 * i];
        a1 += v * Wfc[2 * i + 1];
    }
    __shared__ float red[2][8];
    int lane = tid & 31, wid = tid >> 5;
    a0 = warp_sum(a0); a1 = warp_sum(a1);
    if (lane == 0) { red[0][wid] = a0; red[1][wid] = a1; }
    __syncthreads();
    if (wid == 0) {
        float r0 = (lane < 8) ? red[0][lane] : 0.f;
        float r1 = (lane < 8) ? red[1][lane] : 0.f;
        r0 = warp_sum(r0); r1 = warp_sum(r1);
        if (lane == 0) {
            out[2 * b + 0] = r0 + bfc[0];
            out[2 * b + 1] = r1 + bfc[1];
        }
    }
}

// ---------------- launch ----------------
extern "C" void kernel_launch(void* const* d_in, const int* in_sizes, int n_in,
                              void* d_out, int out_size) {
    const float* tseq = (const float*)d_in[0];
    const float* pseq = (const float*)d_in[1];
    const float* Wc  = (const float*)d_in[2];
    const float* bc  = (const float*)d_in[3];
    const float* gp  = (const float*)d_in[4];
    const float* bp  = (const float*)d_in[5];
    const float* W1  = (const float*)d_in[6];
    const float* b1  = (const float*)d_in[7];
    const float* W2  = (const float*)d_in[8];
    const float* b2  = (const float*)d_in[9];
    const float* g1  = (const float*)d_in[10];
    const float* bn1 = (const float*)d_in[11];
    const float* g2  = (const float*)d_in[12];
    const float* bn2 = (const float*)d_in[13];
    const float* Wfc = (const float*)d_in[14];
    const float* bfc = (const float*)d_in[15];
    float* out = (float*)d_out;

    float *x, *enc, *pbias, *part, *pe;
    __half *xq, *xhi, *phi, *plo, *ffhi;
    __half *w1h, *w2h, *wch;
    cudaGetSymbolAddress((void**)&x, g_x);
    cudaGetSymbolAddress((void**)&enc, g_enc);
    cudaGetSymbolAddress((void**)&pbias, g_pbias);
    cudaGetSymbolAddress((void**)&part, g_part);
    cudaGetSymbolAddress((void**)&pe, g_pe);
    cudaGetSymbolAddress((void**)&xq, g_xq);
    cudaGetSymbolAddress((void**)&xhi, g_xhi);
    cudaGetSymbolAddress((void**)&phi, g_phi);
    cudaGetSymbolAddress((void**)&plo, g_plo);
    cudaGetSymbolAddress((void**)&ffhi, g_ffhi);
    cudaGetSymbolAddress((void**)&w1h, g_w1h);
    cudaGetSymbolAddress((void**)&w2h, g_w2h);
    cudaGetSymbolAddress((void**)&wch, g_wch);
    float* part0 = part;
    float* part1 = part + (size_t)M_ * D_;

    cudaFuncSetAttribute(attn_kernel, cudaFuncAttributeMaxDynamicSharedMemorySize, ATTN_SMEM);
    cudaFuncSetAttribute((mma_gemm<1, 0, 64>), cudaFuncAttributeMaxDynamicSharedMemorySize, GEMM_SMEM_T0_64);
    cudaFuncSetAttribute((mma_gemm<2, 0, 64>), cudaFuncAttributeMaxDynamicSharedMemorySize, GEMM_SMEM_T0_64);
    cudaFuncSetAttribute((mma_gemm<2, 1, 32>), cudaFuncAttributeMaxDynamicSharedMemorySize, GEMM_SMEM_T1_32);

    // weight transpose + fp16 convert (tiny, one-time per launch)
    wconv_kernel<<<dim3(D_ / 32, FF_ / 32), dim3(32, 8)>>>(W1, w1h, D_, FF_);
    wconv_kernel<<<dim3(FF_ / 32, D_ / 32), dim3(32, 8)>>>(W2, w2h, FF_, D_);
    wconv_kernel<<<dim3(D_ / 32, D_ / 32),  dim3(32, 8)>>>(Wc, wch, D_, D_);

    const int total = M_ * D_;
    pe_kernel<<<(S_ * D_ + 255) / 256, 256>>>(pe);
    add_pe_kernel<<<(total + 255) / 256, 256>>>(tseq, pe, x, xq);
    pool_kernel<<<(total + 255) / 256, 256>>>(pseq, phi, plo);

    // param encoder: enc = LN(pooled @ Wc + bc)  (split-K=2, exact 2-term A)
    mma_gemm<2, 1, 32><<<dim3(D_ / BNT, M_ / BMT, 2), 256, GEMM_SMEM_T1_32>>>(
        phi, plo, wch, nullptr, part0, nullptr, M_, D_, D_);
    ln_kernel<0><<<M_, 192>>>(part0, part1, nullptr, bc, gp, bp, enc, nullptr);

    // layer-invariant attention bias
    pbias_kernel<<<B_ * H_, 256>>>(enc, pbias);

    for (int l = 0; l < NLAYERS; l++) {
        attn_kernel<<<B_ * H_, 256, ATTN_SMEM>>>(xq, pbias, part0);
        ln_kernel<1><<<M_, 192>>>(x, part0, nullptr, nullptr, g1, bn1, x, xhi);
        // FFN1: single-fp16 A, gelu -> single fp16 ff   (BKS=64)
        mma_gemm<1, 0, 64><<<dim3(FF_ / BNT, M_ / BMT), 256, GEMM_SMEM_T0_64>>>(
            xhi, nullptr, w1h, b1, nullptr, ffhi, M_, FF_, D_);
        // FFN2: single-fp16 A, split-K=2 -> two fp32 partials, b2 folded into LN
        mma_gemm<2, 0, 64><<<dim3(D_ / BNT, M_ / BMT, 2), 256, GEMM_SMEM_T0_64>>>(
            ffhi, nullptr, w2h, nullptr, part0, nullptr, M_, D_, FF_);
        // end-of-layer LN: x + 2 partials + b2; fp32 x + fp16 copy for next attn
        ln_kernel<1><<<M_, 192>>>(x, part0, part1, b2, g2, bn2, x, xq);
    }

    fc_kernel<<<B_, 256>>>(x, Wfc, bfc, out);
}

// round 15
// speedup vs baseline: 1.0390x; 1.0032x over previous
#include <cuda_runtime.h>
#include <cuda_fp16.h>
#include <math.h>
#include <stdint.h>

// ---------------- problem constants ----------------
#define B_   64
#define S_   100
#define D_   768
#define H_   8
#define HD_  96
#define P_   8
#define FF_  3072
#define M_   (B_ * S_)            // 6400 rows
#define NLAYERS 4
#define EPS_ 1e-5f
#define INV_SQRT_HD 0.10206207261596575f   // 1/sqrt(96)

// ---------------- device scratch ----------------
__device__ float g_x[M_ * D_];
__device__ float g_enc[M_ * D_];
__device__ float g_pbias[B_ * H_ * S_ * S_];
__device__ float g_part[2][M_ * D_];   // split-K fp32 partials
__device__ float g_pe[S_ * D_];
__device__ float g_fcpart[4 * 128];    // fc split partials

__device__ __half g_xq[M_ * D_];     // fp16 of attn input (layer input)
__device__ __half g_xhi[M_ * D_];    // fp16 of LN1 output (FFN1 input)
__device__ __half g_phi[M_ * D_];
__device__ __half g_plo[M_ * D_];
__device__ __half g_ffhi[(size_t)M_ * FF_];
__device__ __half g_w1h[(size_t)FF_ * D_];   // [N=3072][K=768] fp16
__device__ __half g_w2h[(size_t)D_ * FF_];   // [N=768][K=3072] fp16
__device__ __half g_wch[(size_t)D_ * D_];    // [N=768][K=768]  fp16

// ============================================================
// PTX helpers (mma.sync / ldmatrix / cp.async — all baseline sm_80+)
// ============================================================
__device__ __forceinline__ uint32_t smem_u32(const void* p) {
    uint32_t a;
    asm("{ .reg .u64 t; cvta.to.shared.u64 t, %1; cvt.u32.u64 %0, t; }" : "=r"(a) : "l"(p));
    return a;
}

#define CP_ASYNC16(dst, src) \
    asm volatile("cp.async.cg.shared.global [%0], [%1], 16;\n" :: "r"(dst), "l"(src) : "memory")
#define CP_COMMIT() asm volatile("cp.async.commit_group;\n" ::: "memory")
#define CP_WAIT0()  asm volatile("cp.async.wait_group 0;\n" ::: "memory")
#define CP_WAIT1()  asm volatile("cp.async.wait_group 1;\n" ::: "memory")

#define LDSM4(r, addr) \
    asm volatile("ldmatrix.sync.aligned.m8n8.x4.shared.b16 {%0,%1,%2,%3}, [%4];" \
        : "=r"((r)[0]), "=r"((r)[1]), "=r"((r)[2]), "=r"((r)[3]) : "r"(addr))

#define LDSM4T(r, addr) \
    asm volatile("ldmatrix.sync.aligned.m8n8.x4.trans.shared.b16 {%0,%1,%2,%3}, [%4];" \
        : "=r"((r)[0]), "=r"((r)[1]), "=r"((r)[2]), "=r"((r)[3]) : "r"(addr))

#define MMA_F16(c, a, b) \
    asm volatile("mma.sync.aligned.m16n8k16.row.col.f32.f16.f16.f32 " \
        "{%0,%1,%2,%3}, {%4,%5,%6,%7}, {%8,%9}, {%0,%1,%2,%3};" \
        : "+f"((c)[0]), "+f"((c)[1]), "+f"((c)[2]), "+f"((c)[3]) \
        : "r"((a)[0]), "r"((a)[1]), "r"((a)[2]), "r"((a)[3]), "r"((b)[0]), "r"((b)[1]))

__device__ __forceinline__ float gelu_exact(float v) {
    return 0.5f * v * (1.0f + erff(v * 0.70710678118654752f));
}
__device__ __forceinline__ void split_f16(float v, __half& h, __half& l) {
    h = __float2half(v);
    l = __float2half(v - __half2float(h));
}

// ============================================================
// GEMM: C[M,N] = A[M,K] @ B^T[N,K] (+ bias)
// TT=1: A = Ah + Al (fp16 pair); TT=0: A = Ah single fp16. B single fp16.
// EPI 1: bias + gelu -> single fp16 out. EPI 2: fp32 partial, z-indexed.
// BKS templated. 3-stage cp.async ring, 2 CTAs/SM.
// ============================================================
#define BMT 128
#define BNT 128
#define NSTAGE 3

template <int BKSv> struct GP {
    static constexpr uint32_t ROWB = BKSv * 2 + 16;
    static constexpr uint32_t MATB = 128u * ROWB;
};
#define GEMM_SMEM_T1_32 (NSTAGE * 3 * GP<32>::MATB)       // 92160 (encoder)
#define GEMM_SMEM_T0_64 (NSTAGE * 2 * GP<64>::MATB)       // 110592 (FFN)

template <int EPI, int TT, int BKSv>
__global__ __launch_bounds__(256, 2)
void mma_gemm(const __half* __restrict__ Ah_, const __half* __restrict__ Al_,
              const __half* __restrict__ Bh_,
              const float* __restrict__ bias,
              float* __restrict__ Cf, __half* __restrict__ Ch,
              int M, int N, int K)
{
    constexpr uint32_t ROWB = GP<BKSv>::ROWB;
    constexpr uint32_t MATB = GP<BKSv>::MATB;
    constexpr int NMAT = TT ? 3 : 2;
    constexpr uint32_t BUFB = NMAT * MATB;
    constexpr int CHUNKS_PER_MAT = 128 * (BKSv / 8);
    constexpr int LOAD_ITERS = NMAT * CHUNKS_PER_MAT / 256;
    constexpr int KHN = BKSv / 16;

    extern __shared__ char dsm[];
    const uint32_t sb0 = smem_u32(dsm);
    const int tid = threadIdx.x;
    const int wid = tid >> 5, lane = tid & 31;
    const int wm = wid >> 1, wn = wid & 1;
    const int row0 = blockIdx.y * BMT, col0 = blockIdx.x * BNT;
    const int Kloc = K / gridDim.z;
    const int koff = blockIdx.z * Kloc;
    const int NS = Kloc / BKSv;

    const __half* Ahp = Ah_ + koff;
    const __half* Alp = TT ? Al_ + koff : nullptr;
    const __half* Bhp = Bh_ + koff;

    float acc[2][8][4];
    #pragma unroll
    for (int i = 0; i < 2; i++)
        #pragma unroll
        for (int j = 0; j < 8; j++)
            #pragma unroll
            for (int k = 0; k < 4; k++) acc[i][j][k] = 0.f;

    const uint32_t aoff = (uint32_t)(wm * 32 + (lane & 15)) * ROWB + (uint32_t)(lane >> 4) * 16;
    const uint32_t boff = (uint32_t)(wn * 64 + ((lane >> 4) << 3) + (lane & 7)) * ROWB
                        + (uint32_t)((lane >> 3) & 1) * 16;
    const uint32_t BOFFM = (TT ? 2u : 1u) * MATB;

    auto load_step = [&](int s) {
        const uint32_t sb = sb0 + (uint32_t)(s % NSTAGE) * BUFB;
        const int k0 = s * BKSv;
        #pragma unroll
        for (int i = 0; i < LOAD_ITERS; i++) {
            int u = i * 256 + tid;
            int mat = u / CHUNKS_PER_MAT;
            int v = u % CHUNKS_PER_MAT;
            int r = v / (BKSv / 8), c = v % (BKSv / 8);
            const __half* src;
            if (TT) {
                if (mat == 0)      src = Ahp + (size_t)(row0 + r) * K + k0 + c * 8;
                else if (mat == 1) src = Alp + (size_t)(row0 + r) * K + k0 + c * 8;
                else               src = Bhp + (size_t)(col0 + r) * K + k0 + c * 8;
            } else {
                if (mat == 0)      src = Ahp + (size_t)(row0 + r) * K + k0 + c * 8;
                else               src = Bhp + (size_t)(col0 + r) * K + k0 + c * 8;
            }
            CP_ASYNC16(sb + (uint32_t)mat * MATB + (uint32_t)r * ROWB + (uint32_t)c * 16, src);
        }
        CP_COMMIT();
    };

    load_step(0);
    if (NS > 1) load_step(1);

    for (int s = 0; s < NS; s++) {
        if (s < NS - 1) { CP_WAIT1(); } else { CP_WAIT0(); }
        __syncthreads();
        if (s + 2 < NS) load_step(s + 2);

        const uint32_t sb = sb0 + (uint32_t)(s % NSTAGE) * BUFB;
        #pragma unroll
        for (int kh = 0; kh < KHN; kh++) {
            uint32_t ah[2][4], al[2][4], b[8][2];
            #pragma unroll
            for (int mf = 0; mf < 2; mf++) {
                LDSM4(ah[mf], sb + aoff + (uint32_t)(mf * 16) * ROWB + (uint32_t)kh * 32);
                if (TT) LDSM4(al[mf], sb + MATB + aoff + (uint32_t)(mf * 16) * ROWB + (uint32_t)kh * 32);
            }
            #pragma unroll
            for (int p = 0; p < 4; p++) {
                uint32_t t[4];
                LDSM4(t, sb + BOFFM + boff + (uint32_t)(p * 16) * ROWB + (uint32_t)kh * 32);
                b[2 * p][0] = t[0]; b[2 * p][1] = t[1];
                b[2 * p + 1][0] = t[2]; b[2 * p + 1][1] = t[3];
            }
            #pragma unroll
            for (int mf = 0; mf < 2; mf++)
                #pragma unroll
                for (int nf = 0; nf < 8; nf++) {
                    MMA_F16(acc[mf][nf], ah[mf], b[nf]);
                    if (TT) MMA_F16(acc[mf][nf], al[mf], b[nf]);
                }
        }
    }

    // ---- epilogue ----
    __syncthreads();
    float* stg = (float*)dsm + wid * (16 * 65);
    const int gcol0 = col0 + wn * 64;
    const float bv0 = (EPI == 2) ? 0.f : bias[gcol0 + lane];
    const float bv1 = (EPI == 2) ? 0.f : bias[gcol0 + 32 + lane];
    const int r1 = lane >> 2, c0 = (lane & 3) * 2;
    float* Cfz = (EPI == 2) ? Cf + (size_t)blockIdx.z * M * N : Cf;

    #pragma unroll
    for (int mf = 0; mf < 2; mf++) {
        #pragma unroll
        for (int nf = 0; nf < 8; nf++) {
            stg[r1 * 65 + nf * 8 + c0]           = acc[mf][nf][0];
            stg[r1 * 65 + nf * 8 + c0 + 1]       = acc[mf][nf][1];
            stg[(r1 + 8) * 65 + nf * 8 + c0]     = acc[mf][nf][2];
            stg[(r1 + 8) * 65 + nf * 8 + c0 + 1] = acc[mf][nf][3];
        }
        __syncwarp();
        const int grow = row0 + wm * 32 + mf * 16;
        #pragma unroll
        for (int r = 0; r < 16; r++) {
            float v0 = stg[r * 65 + lane] + bv0;
            float v1 = stg[r * 65 + 32 + lane] + bv1;
            if (EPI == 1) {
                v0 = gelu_exact(v0);
                v1 = gelu_exact(v1);
                size_t base = (size_t)(grow + r) * N + gcol0;
                Ch[base + lane] = __float2half(v0);
                Ch[base + 32 + lane] = __float2half(v1);
            } else {
                size_t base = (size_t)(grow + r) * N + gcol0;
                Cfz[base + lane] = v0;
                Cfz[base + 32 + lane] = v1;
            }
        }
        __syncwarp();
    }
}

// ============================================================
// weight transpose + fp16 convert
// ============================================================
__global__ void wconv_kernel(const float* __restrict__ W, __half* __restrict__ Th,
                             int K, int N) {
    __shared__ float t[32][33];
    int k0 = blockIdx.x * 32, n0 = blockIdx.y * 32;
    int tx = threadIdx.x, ty = threadIdx.y;
    #pragma unroll
    for (int i = 0; i < 4; i++)
        t[ty + i * 8][tx] = W[(size_t)(k0 + ty + i * 8) * N + n0 + tx];
    __syncthreads();
    #pragma unroll
    for (int i = 0; i < 4; i++) {
        int n = n0 + ty + i * 8, k = k0 + tx;
        Th[(size_t)n * K + k] = __float2half(t[tx][ty + i * 8]);
    }
}

// ---------------- positional-encoding table ----------------
__global__ void pe_kernel(float* __restrict__ pe) {
    int idx = blockIdx.x * 256 + threadIdx.x;
    if (idx >= S_ * D_) return;
    int d = idx % D_;
    int s = idx / D_;
    int i2 = d & ~1;
    float div = expf((float)i2 * (-9.210340371976184f / (float)D_));
    float ang = (float)s * div;
    pe[idx] = (d & 1) ? cosf(ang) : sinf(ang);
}

// ---------------- x = template + pe; also emit fp16 copy ----------------
__global__ void add_pe_kernel(const float* __restrict__ t, const float* __restrict__ pe,
                              float* __restrict__ x, __half* __restrict__ xq) {
    int idx = blockIdx.x * 256 + threadIdx.x;
    if (idx >= M_ * D_) return;
    float v = t[idx] + pe[idx % (S_ * D_)];
    x[idx] = v;
    xq[idx] = __float2half(v);
}

// ---------------- pooled = mean over P, emitted as fp16 hi/lo ----------------
__global__ void pool_kernel(const float* __restrict__ ps,
                            __half* __restrict__ ph, __half* __restrict__ pl) {
    int idx = blockIdx.x * 256 + threadIdx.x;
    if (idx >= M_ * D_) return;
    int bs = idx / D_;
    int c  = idx % D_;
    const float* base = ps + (size_t)bs * (P_ * D_) + c;
    float s = 0.f;
    #pragma unroll
    for (int p = 0; p < P_; p++) s += base[p * D_];
    float m = s * (1.0f / P_);
    __half h, l;
    split_f16(m, h, l);
    ph[idx] = h; pl[idx] = l;
}

// ---------------- block-reduce helper ----------------
__device__ __forceinline__ float warp_sum(float v) {
    #pragma unroll
    for (int o = 16; o; o >>= 1) v += __shfl_down_sync(0xffffffffu, v, o);
    return v;
}

// ---------------- LayerNorm (row length 768), 192 threads, float4 path ----------------
template <int F16OUT>
__global__ __launch_bounds__(192)
void ln_kernel(const float* __restrict__ x,
               const float* __restrict__ rp1, const float* __restrict__ rp2,
               const float* __restrict__ colbias,
               const float* __restrict__ g, const float* __restrict__ b,
               float* __restrict__ out, __half* __restrict__ oh) {
    const int row = blockIdx.x;
    const int tid = threadIdx.x;            // 0..191
    const int c = tid * 4;
    const size_t off = (size_t)row * D_ + c;

    float4 t = *(const float4*)(x + off);
    if (rp1) { float4 r = *(const float4*)(rp1 + off); t.x += r.x; t.y += r.y; t.z += r.z; t.w += r.w; }
    if (rp2) { float4 r = *(const float4*)(rp2 + off); t.x += r.x; t.y += r.y; t.z += r.z; t.w += r.w; }
    if (colbias) { float4 r = *(const float4*)(colbias + c); t.x += r.x; t.y += r.y; t.z += r.z; t.w += r.w; }

    float s = t.x + t.y + t.z + t.w;
    float s2 = t.x * t.x + t.y * t.y + t.z * t.z + t.w * t.w;

    __shared__ float red[2][6];
    __shared__ float stat[2];
    int lane = tid & 31, wid = tid >> 5;
    s = warp_sum(s); s2 = warp_sum(s2);
    if (lane == 0) { red[0][wid] = s; red[1][wid] = s2; }
    __syncthreads();
    if (tid == 0) {
        float a = 0.f, cc = 0.f;
        #pragma unroll
        for (int i = 0; i < 6; i++) { a += red[0][i]; cc += red[1][i]; }
        float mean = a * (1.0f / D_);
        float var = cc * (1.0f / D_) - mean * mean;
        stat[0] = mean;
        stat[1] = rsqrtf(var + EPS_);
    }
    __syncthreads();
    const float mean = stat[0], inv = stat[1];

    float4 gg = *(const float4*)(g + c);
    float4 bb = *(const float4*)(b + c);
    float4 o;
    o.x = (t.x - mean) * inv * gg.x + bb.x;
    o.y = (t.y - mean) * inv * gg.y + bb.y;
    o.z = (t.z - mean) * inv * gg.z + bb.z;
    o.w = (t.w - mean) * inv * gg.w + bb.w;
    *(float4*)(out + off) = o;
    if (F16OUT) {
        __half2 h01 = __floats2half2_rn(o.x, o.y);
        __half2 h23 = __floats2half2_rn(o.z, o.w);
        uint2 pk = make_uint2(*(uint32_t*)&h01, *(uint32_t*)&h23);
        *(uint2*)(oh + off) = pk;
    }
}

// ---------------- param_bias (symmetric, runs once) ----------------
__global__ __launch_bounds__(256)
void pbias_kernel(const float* __restrict__ enc, float* __restrict__ pbias) {
    __shared__ float Es[112 * 97];
    const int b = blockIdx.x >> 3;
    const int h = blockIdx.x & 7;
    const int tid = threadIdx.x;
    const float* src = enc + (size_t)(b * S_) * D_ + h * HD_;

    for (int i = tid; i < 112 * 96; i += 256) {
        int s = i / 96, d = i - s * 96;
        Es[s * 97 + d] = (s < S_) ? src[(size_t)s * D_ + d] : 0.f;
    }
    __syncthreads();

    const int tx = tid & 15, ty = tid >> 4;
    float acc[7][7];
    #pragma unroll
    for (int ii = 0; ii < 7; ii++)
        #pragma unroll
        for (int jj = 0; jj < 7; jj++) acc[ii][jj] = 0.f;

    for (int d = 0; d < 96; d++) {
        float a[7], bb[7];
        #pragma unroll
        for (int ii = 0; ii < 7; ii++) a[ii]  = Es[(ty + 16 * ii) * 97 + d];
        #pragma unroll
        for (int jj = 0; jj < 7; jj++) bb[jj] = Es[(tx + 16 * jj) * 97 + d];
        #pragma unroll
        for (int ii = 0; ii < 7; ii++)
            #pragma unroll
            for (int jj = 0; jj < 7; jj++)
                if (jj >= ii) acc[ii][jj] += a[ii] * bb[jj];
    }

    float* dst = pbias + (size_t)blockIdx.x * (S_ * S_);
    #pragma unroll
    for (int ii = 0; ii < 7; ii++) {
        int i = ty + 16 * ii;
        if (i >= S_) continue;
        #pragma unroll
        for (int jj = 0; jj < 7; jj++) {
            if (jj < ii) continue;
            int j = tx + 16 * jj;
            if (j < S_) {
                float v = acc[ii][jj] * INV_SQRT_HD;
                dst[i * S_ + j] = v;
                if (jj > ii) dst[j * S_ + i] = v;
            }
        }
    }
}

// ---------------- fused attention on tensor cores ----------------
#define QSW 104
#define SSW 120
#define ATTN_SMEM (112 * QSW * 2 + 112 * SSW * 2)   // 50176
__global__ __launch_bounds__(256, 3)
void attn_kernel(const __half* __restrict__ xq, const float* __restrict__ pbias,
                 float* __restrict__ out) {
    extern __shared__ char asm_[];
    __half* Qh = (__half*)asm_;
    __half* Ss = Qh + 112 * QSW;
    const uint32_t qb = smem_u32(Qh);
    const uint32_t sbS = smem_u32(Ss);

    const int b = blockIdx.x >> 3;
    const int h = blockIdx.x & 7;
    const int tid = threadIdx.x;
    const int wid = tid >> 5, lane = tid & 31;

    const __half* src = xq + (size_t)(b * S_) * D_ + h * HD_;
    for (int i = tid; i < 112 * 12; i += 256) {
        int s = i / 12, c = i % 12;
        uint4 v = make_uint4(0u, 0u, 0u, 0u);
        if (s < S_) v = *(const uint4*)(src + (size_t)s * D_ + c * 8);
        *(uint4*)(Qh + s * QSW + c * 8) = v;
    }
    __syncthreads();

    // ---- matmul1: scores ----
    if (wid < 7) {
        float acc[14][4];
        #pragma unroll
        for (int i = 0; i < 14; i++)
            #pragma unroll
            for (int k = 0; k < 4; k++) acc[i][k] = 0.f;

        const uint32_t aoff = qb + (uint32_t)((wid * 16 + (lane & 15)) * 208 + (lane >> 4) * 16);
        const uint32_t boff = qb + (uint32_t)((((lane >> 4) << 3) + (lane & 7)) * 208
                                              + ((lane >> 3) & 1) * 16);
        #pragma unroll
        for (int k = 0; k < 6; k++) {
            uint32_t a[4];
            LDSM4(a, aoff + k * 32);
            #pragma unroll
            for (int p = 0; p < 7; p++) {
                uint32_t t[4];
                LDSM4(t, boff + (uint32_t)(p * 16 * 208) + k * 32);
                uint32_t b0[2] = {t[0], t[1]}, b1[2] = {t[2], t[3]};
                MMA_F16(acc[2 * p], a, b0);
                MMA_F16(acc[2 * p + 1], a, b1);
            }
        }
        const float* pb = pbias + (size_t)blockIdx.x * (S_ * S_);
        const int r = lane >> 2, c0 = (lane & 3) * 2;
        const int i0 = wid * 16 + r, i1 = i0 + 8;
        #pragma unroll
        for (int nf = 0; nf < 14; nf++) {
            int j = nf * 8 + c0;
            float p00 = (i0 < S_ && j < S_)     ? pb[i0 * S_ + j]     : 0.f;
            float p01 = (i0 < S_ && j + 1 < S_) ? pb[i0 * S_ + j + 1] : 0.f;
            float p10 = (i1 < S_ && j < S_)     ? pb[i1 * S_ + j]     : 0.f;
            float p11 = (i1 < S_ && j + 1 < S_) ? pb[i1 * S_ + j + 1] : 0.f;
            Ss[i0 * SSW + j]     = __float2half(acc[nf][0] * INV_SQRT_HD + p00);
            Ss[i0 * SSW + j + 1] = __float2half(acc[nf][1] * INV_SQRT_HD + p01);
            Ss[i1 * SSW + j]     = __float2half(acc[nf][2] * INV_SQRT_HD + p10);
            Ss[i1 * SSW + j + 1] = __float2half(acc[nf][3] * INV_SQRT_HD + p11);
        }
    }
    __syncthreads();

    // ---- softmax: warp-parallel, each warp owns rows wid, wid+8, ... ----
    for (int r = wid; r < S_; r += 8) {
        __half* row = Ss + r * SSW;
        float v[4];
        #pragma unroll
        for (int k = 0; k < 4; k++) {
            int j = lane + 32 * k;
            v[k] = (j < S_) ? __half2float(row[j]) : -1e30f;
        }
        float m = fmaxf(fmaxf(v[0], v[1]), fmaxf(v[2], v[3]));
        #pragma unroll
        for (int o = 16; o; o >>= 1) m = fmaxf(m, __shfl_xor_sync(0xffffffffu, m, o));
        float e[4];
        float s = 0.f;
        #pragma unroll
        for (int k = 0; k < 4; k++) {
            int j = lane + 32 * k;
            e[k] = (j < S_) ? expf(v[k] - m) : 0.f;
            s += e[k];
        }
        #pragma unroll
        for (int o = 16; o; o >>= 1) s += __shfl_xor_sync(0xffffffffu, s, o);
        float inv = 1.0f / s;
        #pragma unroll
        for (int k = 0; k < 4; k++) {
            int j = lane + 32 * k;
            if (j < 112) row[j] = __float2half((j < S_) ? e[k] * inv : 0.f);
        }
    }
    __syncthreads();

    // ---- matmul2: out = P Q ----
    if (wid < 7) {
        float acc[12][4];
        #pragma unroll
        for (int i = 0; i < 12; i++)
            #pragma unroll
            for (int k = 0; k < 4; k++) acc[i][k] = 0.f;

        const uint32_t aoff = sbS + (uint32_t)((wid * 16 + (lane & 15)) * 240 + (lane >> 4) * 16);
        const uint32_t btr = qb + (uint32_t)((((lane >> 3) & 1) * 8 + (lane & 7)) * 208
                                             + ((lane >> 4) * 8) * 2);
        #pragma unroll
        for (int k = 0; k < 7; k++) {
            uint32_t a[4];
            LDSM4(a, aoff + k * 32);
            #pragma unroll
            for (int p = 0; p < 6; p++) {
                uint32_t t[4];
                LDSM4T(t, btr + (uint32_t)(k * 16 * 208) + (uint32_t)(p * 32));
                uint32_t b0[2] = {t[0], t[1]}, b1[2] = {t[2], t[3]};
                MMA_F16(acc[2 * p], a, b0);
                MMA_F16(acc[2 * p + 1], a, b1);
            }
        }
        float* dst = out + (size_t)(b * S_) * D_ + h * HD_;
        const int r = lane >> 2, c0 = (lane & 3) * 2;
        const int i0 = wid * 16 + r, i1 = i0 + 8;
        #pragma unroll
        for (int nf = 0; nf < 12; nf++) {
            int d = nf * 8 + c0;
            if (i0 < S_) {
                dst[(size_t)i0 * D_ + d]     = acc[nf][0];
                dst[(size_t)i0 * D_ + d + 1] = acc[nf][1];
            }
            if (i1 < S_) {
                dst[(size_t)i1 * D_ + d]     = acc[nf][2];
                dst[(size_t)i1 * D_ + d + 1] = acc[nf][3];
            }
        }
    }
}

// ---------------- final classifier: split into 4 K-chunks + reduce ----------------
__global__ void fc_partial_kernel(const float* __restrict__ x, const float* __restrict__ Wfc,
                                  float* __restrict__ partial) {
    const int b = blockIdx.x;
    const int z = blockIdx.y;          // 0..3, each covers 19200 elements
    const int tid = threadIdx.x;
    const int base = z * 19200;
    const float* xr = x + (size_t)b * (S_ * D_) + base;
    const float* wr = Wfc + 2 * (size_t)base;
    float a0 = 0.f, a1 = 0.f;
    for (int i = tid; i < 19200; i += 256) {
        float v = xr[i];
        a0 += v * wr[2 * i];
        a1 += v * wr[2 * i + 1];
    }
    __shared__ float red[2][8];
    int lane = tid & 31, wid = tid >> 5;
    a0 = warp_sum(a0); a1 = warp_sum(a1);
    if (lane == 0) { red[0][wid] = a0; red[1][wid] = a1; }
    __syncthreads();
    if (wid == 0) {
        float r0 = (lane < 8) ? red[0][lane] : 0.f;
        float r1 = (lane < 8) ? red[1][lane] : 0.f;
        r0 = warp_sum(r0); r1 = warp_sum(r1);
        if (lane == 0) {
            partial[z * 128 + 2 * b + 0] = r0;
            partial[z * 128 + 2 * b + 1] = r1;
        }
    }
}

__global__ void fc_reduce_kernel(const float* __restrict__ partial,
                                 const float* __restrict__ bfc, float* __restrict__ out) {
    int i = threadIdx.x;   // 0..127
    out[i] = partial[i] + partial[128 + i] + partial[256 + i] + partial[384 + i]
           + bfc[i & 1];
}

// ---------------- launch ----------------
extern "C" void kernel_launch(void* const* d_in, const int* in_sizes, int n_in,
                              void* d_out, int out_size) {
    const float* tseq = (const float*)d_in[0];
    const float* pseq = (const float*)d_in[1];
    const float* Wc  = (const float*)d_in[2];
    const float* bc  = (const float*)d_in[3];
    const float* gp  = (const float*)d_in[4];
    const float* bp  = (const float*)d_in[5];
    const float* W1  = (const float*)d_in[6];
    const float* b1  = (const float*)d_in[7];
    const float* W2  = (const float*)d_in[8];
    const float* b2  = (const float*)d_in[9];
    const float* g1  = (const float*)d_in[10];
    const float* bn1 = (const float*)d_in[11];
    const float* g2  = (const float*)d_in[12];
    const float* bn2 = (const float*)d_in[13];
    const float* Wfc = (const float*)d_in[14];
    const float* bfc = (const float*)d_in[15];
    float* out = (float*)d_out;

    float *x, *enc, *pbias, *part, *pe, *fcp;
    __half *xq, *xhi, *phi, *plo, *ffhi;
    __half *w1h, *w2h, *wch;
    cudaGetSymbolAddress((void**)&x, g_x);
    cudaGetSymbolAddress((void**)&enc, g_enc);
    cudaGetSymbolAddress((void**)&pbias, g_pbias);
    cudaGetSymbolAddress((void**)&part, g_part);
    cudaGetSymbolAddress((void**)&pe, g_pe);
    cudaGetSymbolAddress((void**)&fcp, g_fcpart);
    cudaGetSymbolAddress((void**)&xq, g_xq);
    cudaGetSymbolAddress((void**)&xhi, g_xhi);
    cudaGetSymbolAddress((void**)&phi, g_phi);
    cudaGetSymbolAddress((void**)&plo, g_plo);
    cudaGetSymbolAddress((void**)&ffhi, g_ffhi);
    cudaGetSymbolAddress((void**)&w1h, g_w1h);
    cudaGetSymbolAddress((void**)&w2h, g_w2h);
    cudaGetSymbolAddress((void**)&wch, g_wch);
    float* part0 = part;
    float* part1 = part + (size_t)M_ * D_;

    cudaFuncSetAttribute(attn_kernel, cudaFuncAttributeMaxDynamicSharedMemorySize, ATTN_SMEM);
    cudaFuncSetAttribute((mma_gemm<1, 0, 64>), cudaFuncAttributeMaxDynamicSharedMemorySize, GEMM_SMEM_T0_64);
    cudaFuncSetAttribute((mma_gemm<2, 0, 64>), cudaFuncAttributeMaxDynamicSharedMemorySize, GEMM_SMEM_T0_64);
    cudaFuncSetAttribute((mma_gemm<2, 1, 32>), cudaFuncAttributeMaxDynamicSharedMemorySize, GEMM_SMEM_T1_32);

    // weight transpose + fp16 convert (tiny, one-time per launch)
    wconv_kernel<<<dim3(D_ / 32, FF_ / 32), dim3(32, 8)>>>(W1, w1h, D_, FF_);
    wconv_kernel<<<dim3(FF_ / 32, D_ / 32), dim3(32, 8)>>>(W2, w2h, FF_, D_);
    wconv_kernel<<<dim3(D_ / 32, D_ / 32),  dim3(32, 8)>>>(Wc, wch, D_, D_);

    const int total = M_ * D_;
    pe_kernel<<<(S_ * D_ + 255) / 256, 256>>>(pe);
    add_pe_kernel<<<(total + 255) / 256, 256>>>(tseq, pe, x, xq);
    pool_kernel<<<(total + 255) / 256, 256>>>(pseq, phi, plo);

    // param encoder: enc = LN(pooled @ Wc + bc)  (split-K=2, exact 2-term A)
    mma_gemm<2, 1, 32><<<dim3(D_ / BNT, M_ / BMT, 2), 256, GEMM_SMEM_T1_32>>>(
        phi, plo, wch, nullptr, part0, nullptr, M_, D_, D_);
    ln_kernel<0><<<M_, 192>>>(part0, part1, nullptr, bc, gp, bp, enc, nullptr);

    // layer-invariant attention bias
    pbias_kernel<<<B_ * H_, 256>>>(enc, pbias);

    for (int l = 0; l < NLAYERS; l++) {
        attn_kernel<<<B_ * H_, 256, ATTN_SMEM>>>(xq, pbias, part0);
        ln_kernel<1><<<M_, 192>>>(x, part0, nullptr, nullptr, g1, bn1, x, xhi);
        // FFN1: single-fp16 A, gelu -> single fp16 ff   (BKS=64)
        mma_gemm<1, 0, 64><<<dim3(FF_ / BNT, M_ / BMT), 256, GEMM_SMEM_T0_64>>>(
            xhi, nullptr, w1h, b1, nullptr, ffhi, M_, FF_, D_);
        // FFN2: single-fp16 A, split-K=2 -> two fp32 partials, b2 folded into LN
        mma_gemm<2, 0, 64><<<dim3(D_ / BNT, M_ / BMT, 2), 256, GEMM_SMEM_T0_64>>>(
            ffhi, nullptr, w2h, nullptr, part0, nullptr, M_, D_, FF_);
        // end-of-layer LN: x + 2 partials + b2; fp32 x + fp16 copy for next attn
        ln_kernel<1><<<M_, 192>>>(x, part0, part1, b2, g2, bn2, x, xq);
    }

    fc_partial_kernel<<<dim3(B_, 4), 256>>>(x, Wfc, fcp);
    fc_reduce_kernel<<<1, 128>>>(fcp, bfc, out);
}

// round 16
// speedup vs baseline: 1.0680x; 1.0278x over previous
#include <cuda_runtime.h>
#include <cuda_fp16.h>
#include <math.h>
#include <stdint.h>

// ---------------- problem constants ----------------
#define B_   64
#define S_   100
#define D_   768
#define H_   8
#define HD_  96
#define P_   8
#define FF_  3072
#define M_   (B_ * S_)            // 6400 rows
#define NLAYERS 4
#define EPS_ 1e-5f
#define INV_SQRT_HD 0.10206207261596575f   // 1/sqrt(96)

// ---------------- device scratch ----------------
__device__ float g_x[M_ * D_];
__device__ float g_enc[M_ * D_];
__device__ float g_pbias[B_ * H_ * S_ * S_];
__device__ float g_part[2][M_ * D_];   // split-K fp32 partials
__device__ float g_pe[S_ * D_];
__device__ float g_fcpart[4 * 128];    // fc split partials

__device__ __half g_xq[M_ * D_];     // fp16 of attn input (layer input)
__device__ __half g_xhi[M_ * D_];    // fp16 of LN1 output (FFN1 input)
__device__ __half g_attn[M_ * D_];   // fp16 attention output
__device__ __half g_phi[M_ * D_];
__device__ __half g_ffhi[(size_t)M_ * FF_];
__device__ __half g_w1h[(size_t)FF_ * D_];   // [N=3072][K=768] fp16
__device__ __half g_w2h[(size_t)D_ * FF_];   // [N=768][K=3072] fp16
__device__ __half g_wch[(size_t)D_ * D_];    // [N=768][K=768]  fp16

// ============================================================
// PTX helpers (mma.sync / ldmatrix / cp.async — all baseline sm_80+)
// ============================================================
__device__ __forceinline__ uint32_t smem_u32(const void* p) {
    uint32_t a;
    asm("{ .reg .u64 t; cvta.to.shared.u64 t, %1; cvt.u32.u64 %0, t; }" : "=r"(a) : "l"(p));
    return a;
}

#define CP_ASYNC16(dst, src) \
    asm volatile("cp.async.cg.shared.global [%0], [%1], 16;\n" :: "r"(dst), "l"(src) : "memory")
#define CP_COMMIT() asm volatile("cp.async.commit_group;\n" ::: "memory")
#define CP_WAIT0()  asm volatile("cp.async.wait_group 0;\n" ::: "memory")
#define CP_WAIT1()  asm volatile("cp.async.wait_group 1;\n" ::: "memory")

#define LDSM4(r, addr) \
    asm volatile("ldmatrix.sync.aligned.m8n8.x4.shared.b16 {%0,%1,%2,%3}, [%4];" \
        : "=r"((r)[0]), "=r"((r)[1]), "=r"((r)[2]), "=r"((r)[3]) : "r"(addr))

#define LDSM4T(r, addr) \
    asm volatile("ldmatrix.sync.aligned.m8n8.x4.trans.shared.b16 {%0,%1,%2,%3}, [%4];" \
        : "=r"((r)[0]), "=r"((r)[1]), "=r"((r)[2]), "=r"((r)[3]) : "r"(addr))

#define MMA_F16(c, a, b) \
    asm volatile("mma.sync.aligned.m16n8k16.row.col.f32.f16.f16.f32 " \
        "{%0,%1,%2,%3}, {%4,%5,%6,%7}, {%8,%9}, {%0,%1,%2,%3};" \
        : "+f"((c)[0]), "+f"((c)[1]), "+f"((c)[2]), "+f"((c)[3]) \
        : "r"((a)[0]), "r"((a)[1]), "r"((a)[2]), "r"((a)[3]), "r"((b)[0]), "r"((b)[1]))

__device__ __forceinline__ float gelu_exact(float v) {
    return 0.5f * v * (1.0f + erff(v * 0.70710678118654752f));
}

// ============================================================
// GEMM: C[M,N] = A[M,K] @ B^T[N,K] (+ bias)
// TT=1: A = Ah + Al (fp16 pair); TT=0: A = Ah single fp16. B single fp16.
// EPI 1: bias + gelu -> single fp16 out. EPI 2: fp32 partial, z-indexed.
// BKS templated. 3-stage cp.async ring, 2 CTAs/SM.
// ============================================================
#define BMT 128
#define BNT 128
#define NSTAGE 3

template <int BKSv> struct GP {
    static constexpr uint32_t ROWB = BKSv * 2 + 16;
    static constexpr uint32_t MATB = 128u * ROWB;
};
#define GEMM_SMEM_T0_64 (NSTAGE * 2 * GP<64>::MATB)       // 110592

template <int EPI, int TT, int BKSv>
__global__ __launch_bounds__(256, 2)
void mma_gemm(const __half* __restrict__ Ah_, const __half* __restrict__ Al_,
              const __half* __restrict__ Bh_,
              const float* __restrict__ bias,
              float* __restrict__ Cf, __half* __restrict__ Ch,
              int M, int N, int K)
{
    constexpr uint32_t ROWB = GP<BKSv>::ROWB;
    constexpr uint32_t MATB = GP<BKSv>::MATB;
    constexpr int NMAT = TT ? 3 : 2;
    constexpr uint32_t BUFB = NMAT * MATB;
    constexpr int CHUNKS_PER_MAT = 128 * (BKSv / 8);
    constexpr int LOAD_ITERS = NMAT * CHUNKS_PER_MAT / 256;
    constexpr int KHN = BKSv / 16;

    extern __shared__ char dsm[];
    const uint32_t sb0 = smem_u32(dsm);
    const int tid = threadIdx.x;
    const int wid = tid >> 5, lane = tid & 31;
    const int wm = wid >> 1, wn = wid & 1;
    const int row0 = blockIdx.y * BMT, col0 = blockIdx.x * BNT;
    const int Kloc = K / gridDim.z;
    const int koff = blockIdx.z * Kloc;
    const int NS = Kloc / BKSv;

    const __half* Ahp = Ah_ + koff;
    const __half* Alp = TT ? Al_ + koff : nullptr;
    const __half* Bhp = Bh_ + koff;

    float acc[2][8][4];
    #pragma unroll
    for (int i = 0; i < 2; i++)
        #pragma unroll
        for (int j = 0; j < 8; j++)
            #pragma unroll
            for (int k = 0; k < 4; k++) acc[i][j][k] = 0.f;

    const uint32_t aoff = (uint32_t)(wm * 32 + (lane & 15)) * ROWB + (uint32_t)(lane >> 4) * 16;
    const uint32_t boff = (uint32_t)(wn * 64 + ((lane >> 4) << 3) + (lane & 7)) * ROWB
                        + (uint32_t)((lane >> 3) & 1) * 16;
    const uint32_t BOFFM = (TT ? 2u : 1u) * MATB;

    auto load_step = [&](int s) {
        const uint32_t sb = sb0 + (uint32_t)(s % NSTAGE) * BUFB;
        const int k0 = s * BKSv;
        #pragma unroll
        for (int i = 0; i < LOAD_ITERS; i++) {
            int u = i * 256 + tid;
            int mat = u / CHUNKS_PER_MAT;
            int v = u % CHUNKS_PER_MAT;
            int r = v / (BKSv / 8), c = v % (BKSv / 8);
            const __half* src;
            if (TT) {
                if (mat == 0)      src = Ahp + (size_t)(row0 + r) * K + k0 + c * 8;
                else if (mat == 1) src = Alp + (size_t)(row0 + r) * K + k0 + c * 8;
                else               src = Bhp + (size_t)(col0 + r) * K + k0 + c * 8;
            } else {
                if (mat == 0)      src = Ahp + (size_t)(row0 + r) * K + k0 + c * 8;
                else               src = Bhp + (size_t)(col0 + r) * K + k0 + c * 8;
            }
            CP_ASYNC16(sb + (uint32_t)mat * MATB + (uint32_t)r * ROWB + (uint32_t)c * 16, src);
        }
        CP_COMMIT();
    };

    load_step(0);
    if (NS > 1) load_step(1);

    for (int s = 0; s < NS; s++) {
        if (s < NS - 1) { CP_WAIT1(); } else { CP_WAIT0(); }
        __syncthreads();
        if (s + 2 < NS) load_step(s + 2);

        const uint32_t sb = sb0 + (uint32_t)(s % NSTAGE) * BUFB;
        #pragma unroll
        for (int kh = 0; kh < KHN; kh++) {
            uint32_t ah[2][4], al[2][4], b[8][2];
            #pragma unroll
            for (int mf = 0; mf < 2; mf++) {
                LDSM4(ah[mf], sb + aoff + (uint32_t)(mf * 16) * ROWB + (uint32_t)kh * 32);
                if (TT) LDSM4(al[mf], sb + MATB + aoff + (uint32_t)(mf * 16) * ROWB + (uint32_t)kh * 32);
            }
            #pragma unroll
            for (int p = 0; p < 4; p++) {
                uint32_t t[4];
                LDSM4(t, sb + BOFFM + boff + (uint32_t)(p * 16) * ROWB + (uint32_t)kh * 32);
                b[2 * p][0] = t[0]; b[2 * p][1] = t[1];
                b[2 * p + 1][0] = t[2]; b[2 * p + 1][1] = t[3];
            }
            #pragma unroll
            for (int mf = 0; mf < 2; mf++)
                #pragma unroll
                for (int nf = 0; nf < 8; nf++) {
                    MMA_F16(acc[mf][nf], ah[mf], b[nf]);
                    if (TT) MMA_F16(acc[mf][nf], al[mf], b[nf]);
                }
        }
    }

    // ---- epilogue ----
    __syncthreads();
    float* stg = (float*)dsm + wid * (16 * 65);
    const int gcol0 = col0 + wn * 64;
    const float bv0 = (EPI == 2) ? 0.f : bias[gcol0 + lane];
    const float bv1 = (EPI == 2) ? 0.f : bias[gcol0 + 32 + lane];
    const int r1 = lane >> 2, c0 = (lane & 3) * 2;
    float* Cfz = (EPI == 2) ? Cf + (size_t)blockIdx.z * M * N : Cf;

    #pragma unroll
    for (int mf = 0; mf < 2; mf++) {
        #pragma unroll
        for (int nf = 0; nf < 8; nf++) {
            stg[r1 * 65 + nf * 8 + c0]           = acc[mf][nf][0];
            stg[r1 * 65 + nf * 8 + c0 + 1]       = acc[mf][nf][1];
            stg[(r1 + 8) * 65 + nf * 8 + c0]     = acc[mf][nf][2];
            stg[(r1 + 8) * 65 + nf * 8 + c0 + 1] = acc[mf][nf][3];
        }
        __syncwarp();
        const int grow = row0 + wm * 32 + mf * 16;
        #pragma unroll
        for (int r = 0; r < 16; r++) {
            float v0 = stg[r * 65 + lane] + bv0;
            float v1 = stg[r * 65 + 32 + lane] + bv1;
            if (EPI == 1) {
                v0 = gelu_exact(v0);
                v1 = gelu_exact(v1);
                size_t base = (size_t)(grow + r) * N + gcol0;
                Ch[base + lane] = __float2half(v0);
                Ch[base + 32 + lane] = __float2half(v1);
            } else {
                size_t base = (size_t)(grow + r) * N + gcol0;
                Cfz[base + lane] = v0;
                Cfz[base + 32 + lane] = v1;
            }
        }
        __syncwarp();
    }
}

// ============================================================
// weight transpose + fp16 convert
// ============================================================
__global__ void wconv_kernel(const float* __restrict__ W, __half* __restrict__ Th,
                             int K, int N) {
    __shared__ float t[32][33];
    int k0 = blockIdx.x * 32, n0 = blockIdx.y * 32;
    int tx = threadIdx.x, ty = threadIdx.y;
    #pragma unroll
    for (int i = 0; i < 4; i++)
        t[ty + i * 8][tx] = W[(size_t)(k0 + ty + i * 8) * N + n0 + tx];
    __syncthreads();
    #pragma unroll
    for (int i = 0; i < 4; i++) {
        int n = n0 + ty + i * 8, k = k0 + tx;
        Th[(size_t)n * K + k] = __float2half(t[tx][ty + i * 8]);
    }
}

// ---------------- positional-encoding table ----------------
__global__ void pe_kernel(float* __restrict__ pe) {
    int idx = blockIdx.x * 256 + threadIdx.x;
    if (idx >= S_ * D_) return;
    int d = idx % D_;
    int s = idx / D_;
    int i2 = d & ~1;
    float div = expf((float)i2 * (-9.210340371976184f / (float)D_));
    float ang = (float)s * div;
    pe[idx] = (d & 1) ? cosf(ang) : sinf(ang);
}

// ---------------- x = template + pe; also emit fp16 copy ----------------
__global__ void add_pe_kernel(const float* __restrict__ t, const float* __restrict__ pe,
                              float* __restrict__ x, __half* __restrict__ xq) {
    int idx = blockIdx.x * 256 + threadIdx.x;
    if (idx >= M_ * D_) return;
    float v = t[idx] + pe[idx % (S_ * D_)];
    x[idx] = v;
    xq[idx] = __float2half(v);
}

// ---------------- pooled = mean over P, emitted as single fp16 ----------------
__global__ void pool_kernel(const float* __restrict__ ps, __half* __restrict__ ph) {
    int idx = blockIdx.x * 256 + threadIdx.x;
    if (idx >= M_ * D_) return;
    int bs = idx / D_;
    int c  = idx % D_;
    const float* base = ps + (size_t)bs * (P_ * D_) + c;
    float s = 0.f;
    #pragma unroll
    for (int p = 0; p < P_; p++) s += base[p * D_];
    ph[idx] = __float2half(s * (1.0f / P_));
}

// ---------------- block-reduce helper ----------------
__device__ __forceinline__ float warp_sum(float v) {
    #pragma unroll
    for (int o = 16; o; o >>= 1) v += __shfl_down_sync(0xffffffffu, v, o);
    return v;
}

// ---------------- LayerNorm (row length 768), 192 threads, float4 path ----------------
// t = x + r1 + r2 + hres(fp16) + colbias (any may be null)
template <int F16OUT>
__global__ __launch_bounds__(192)
void ln_kernel(const float* __restrict__ x,
               const float* __restrict__ rp1, const float* __restrict__ rp2,
               const __half* __restrict__ hres,
               const float* __restrict__ colbias,
               const float* __restrict__ g, const float* __restrict__ b,
               float* __restrict__ out, __half* __restrict__ oh) {
    const int row = blockIdx.x;
    const int tid = threadIdx.x;            // 0..191
    const int c = tid * 4;
    const size_t off = (size_t)row * D_ + c;

    float4 t = *(const float4*)(x + off);
    if (rp1) { float4 r = *(const float4*)(rp1 + off); t.x += r.x; t.y += r.y; t.z += r.z; t.w += r.w; }
    if (rp2) { float4 r = *(const float4*)(rp2 + off); t.x += r.x; t.y += r.y; t.z += r.z; t.w += r.w; }
    if (hres) {
        uint2 pk = *(const uint2*)(hres + off);
        __half2 h01 = *(__half2*)&pk.x;
        __half2 h23 = *(__half2*)&pk.y;
        float2 f01 = __half22float2(h01);
        float2 f23 = __half22float2(h23);
        t.x += f01.x; t.y += f01.y; t.z += f23.x; t.w += f23.y;
    }
    if (colbias) { float4 r = *(const float4*)(colbias + c); t.x += r.x; t.y += r.y; t.z += r.z; t.w += r.w; }

    float s = t.x + t.y + t.z + t.w;
    float s2 = t.x * t.x + t.y * t.y + t.z * t.z + t.w * t.w;

    __shared__ float red[2][6];
    __shared__ float stat[2];
    int lane = tid & 31, wid = tid >> 5;
    s = warp_sum(s); s2 = warp_sum(s2);
    if (lane == 0) { red[0][wid] = s; red[1][wid] = s2; }
    __syncthreads();
    if (tid == 0) {
        float a = 0.f, cc = 0.f;
        #pragma unroll
        for (int i = 0; i < 6; i++) { a += red[0][i]; cc += red[1][i]; }
        float mean = a * (1.0f / D_);
        float var = cc * (1.0f / D_) - mean * mean;
        stat[0] = mean;
        stat[1] = rsqrtf(var + EPS_);
    }
    __syncthreads();
    const float mean = stat[0], inv = stat[1];

    float4 gg = *(const float4*)(g + c);
    float4 bb = *(const float4*)(b + c);
    float4 o;
    o.x = (t.x - mean) * inv * gg.x + bb.x;
    o.y = (t.y - mean) * inv * gg.y + bb.y;
    o.z = (t.z - mean) * inv * gg.z + bb.z;
    o.w = (t.w - mean) * inv * gg.w + bb.w;
    *(float4*)(out + off) = o;
    if (F16OUT) {
        __half2 h01 = __floats2half2_rn(o.x, o.y);
        __half2 h23 = __floats2half2_rn(o.z, o.w);
        uint2 pk = make_uint2(*(uint32_t*)&h01, *(uint32_t*)&h23);
        *(uint2*)(oh + off) = pk;
    }
}

// ---------------- param_bias (symmetric, runs once) ----------------
__global__ __launch_bounds__(256)
void pbias_kernel(const float* __restrict__ enc, float* __restrict__ pbias) {
    __shared__ float Es[112 * 97];
    const int b = blockIdx.x >> 3;
    const int h = blockIdx.x & 7;
    const int tid = threadIdx.x;
    const float* src = enc + (size_t)(b * S_) * D_ + h * HD_;

    for (int i = tid; i < 112 * 96; i += 256) {
        int s = i / 96, d = i - s * 96;
        Es[s * 97 + d] = (s < S_) ? src[(size_t)s * D_ + d] : 0.f;
    }
    __syncthreads();

    const int tx = tid & 15, ty = tid >> 4;
    float acc[7][7];
    #pragma unroll
    for (int ii = 0; ii < 7; ii++)
        #pragma unroll
        for (int jj = 0; jj < 7; jj++) acc[ii][jj] = 0.f;

    for (int d = 0; d < 96; d++) {
        float a[7], bb[7];
        #pragma unroll
        for (int ii = 0; ii < 7; ii++) a[ii]  = Es[(ty + 16 * ii) * 97 + d];
        #pragma unroll
        for (int jj = 0; jj < 7; jj++) bb[jj] = Es[(tx + 16 * jj) * 97 + d];
        #pragma unroll
        for (int ii = 0; ii < 7; ii++)
            #pragma unroll
            for (int jj = 0; jj < 7; jj++)
                if (jj >= ii) acc[ii][jj] += a[ii] * bb[jj];
    }

    float* dst = pbias + (size_t)blockIdx.x * (S_ * S_);
    #pragma unroll
    for (int ii = 0; ii < 7; ii++) {
        int i = ty + 16 * ii;
        if (i >= S_) continue;
        #pragma unroll
        for (int jj = 0; jj < 7; jj++) {
            if (jj < ii) continue;
            int j = tx + 16 * jj;
            if (j < S_) {
                float v = acc[ii][jj] * INV_SQRT_HD;
                dst[i * S_ + j] = v;
                if (jj > ii) dst[j * S_ + i] = v;
            }
        }
    }
}

// ---------------- fused attention on tensor cores ----------------
#define QSW 104
#define SSW 120
#define ATTN_SMEM (112 * QSW * 2 + 112 * SSW * 2)   // 50176
__global__ __launch_bounds__(256, 3)
void attn_kernel(const __half* __restrict__ xq, const float* __restrict__ pbias,
                 __half* __restrict__ out) {
    extern __shared__ char asm_[];
    __half* Qh = (__half*)asm_;
    __half* Ss = Qh + 112 * QSW;
    const uint32_t qb = smem_u32(Qh);
    const uint32_t sbS = smem_u32(Ss);

    const int b = blockIdx.x >> 3;
    const int h = blockIdx.x & 7;
    const int tid = threadIdx.x;
    const int wid = tid >> 5, lane = tid & 31;

    const __half* src = xq + (size_t)(b * S_) * D_ + h * HD_;
    for (int i = tid; i < 112 * 12; i += 256) {
        int s = i / 12, c = i % 12;
        uint4 v = make_uint4(0u, 0u, 0u, 0u);
        if (s < S_) v = *(const uint4*)(src + (size_t)s * D_ + c * 8);
        *(uint4*)(Qh + s * QSW + c * 8) = v;
    }
    __syncthreads();

    // ---- matmul1: scores ----
    if (wid < 7) {
        float acc[14][4];
        #pragma unroll
        for (int i = 0; i < 14; i++)
            #pragma unroll
            for (int k = 0; k < 4; k++) acc[i][k] = 0.f;

        const uint32_t aoff = qb + (uint32_t)((wid * 16 + (lane & 15)) * 208 + (lane >> 4) * 16);
        const uint32_t boff = qb + (uint32_t)((((lane >> 4) << 3) + (lane & 7)) * 208
                                              + ((lane >> 3) & 1) * 16);
        #pragma unroll
        for (int k = 0; k < 6; k++) {
            uint32_t a[4];
            LDSM4(a, aoff + k * 32);
            #pragma unroll
            for (int p = 0; p < 7; p++) {
                uint32_t t[4];
                LDSM4(t, boff + (uint32_t)(p * 16 * 208) + k * 32);
                uint32_t b0[2] = {t[0], t[1]}, b1[2] = {t[2], t[3]};
                MMA_F16(acc[2 * p], a, b0);
                MMA_F16(acc[2 * p + 1], a, b1);
            }
        }
        const float* pb = pbias + (size_t)blockIdx.x * (S_ * S_);
        const int r = lane >> 2, c0 = (lane & 3) * 2;
        const int i0 = wid * 16 + r, i1 = i0 + 8;
        #pragma unroll
        for (int nf = 0; nf < 14; nf++) {
            int j = nf * 8 + c0;
            float p00 = (i0 < S_ && j < S_)     ? pb[i0 * S_ + j]     : 0.f;
            float p01 = (i0 < S_ && j + 1 < S_) ? pb[i0 * S_ + j + 1] : 0.f;
            float p10 = (i1 < S_ && j < S_)     ? pb[i1 * S_ + j]     : 0.f;
            float p11 = (i1 < S_ && j + 1 < S_) ? pb[i1 * S_ + j + 1] : 0.f;
            Ss[i0 * SSW + j]     = __float2half(acc[nf][0] * INV_SQRT_HD + p00);
            Ss[i0 * SSW + j + 1] = __float2half(acc[nf][1] * INV_SQRT_HD + p01);
            Ss[i1 * SSW + j]     = __float2half(acc[nf][2] * INV_SQRT_HD + p10);
            Ss[i1 * SSW + j + 1] = __float2half(acc[nf][3] * INV_SQRT_HD + p11);
        }
    }
    __syncthreads();

    // ---- softmax: warp-parallel, each warp owns rows wid, wid+8, ... ----
    for (int r = wid; r < S_; r += 8) {
        __half* row = Ss + r * SSW;
        float v[4];
        #pragma unroll
        for (int k = 0; k < 4; k++) {
            int j = lane + 32 * k;
            v[k] = (j < S_) ? __half2float(row[j]) : -1e30f;
        }
        float m = fmaxf(fmaxf(v[0], v[1]), fmaxf(v[2], v[3]));
        #pragma unroll
        for (int o = 16; o; o >>= 1) m = fmaxf(m, __shfl_xor_sync(0xffffffffu, m, o));
        float e[4];
        float s = 0.f;
        #pragma unroll
        for (int k = 0; k < 4; k++) {
            int j = lane + 32 * k;
            e[k] = (j < S_) ? expf(v[k] - m) : 0.f;
            s += e[k];
        }
        #pragma unroll
        for (int o = 16; o; o >>= 1) s += __shfl_xor_sync(0xffffffffu, s, o);
        float inv = 1.0f / s;
        #pragma unroll
        for (int k = 0; k < 4; k++) {
            int j = lane + 32 * k;
            if (j < 112) row[j] = __float2half((j < S_) ? e[k] * inv : 0.f);
        }
    }
    __syncthreads();

    // ---- matmul2: out = P Q (fp16 half2 stores) ----
    if (wid < 7) {
        float acc[12][4];
        #pragma unroll
        for (int i = 0; i < 12; i++)
            #pragma unroll
            for (int k = 0; k < 4; k++) acc[i][k] = 0.f;

        const uint32_t aoff = sbS + (uint32_t)((wid * 16 + (lane & 15)) * 240 + (lane >> 4) * 16);
        const uint32_t btr = qb + (uint32_t)((((lane >> 3) & 1) * 8 + (lane & 7)) * 208
                                             + ((lane >> 4) * 8) * 2);
        #pragma unroll
        for (int k = 0; k < 7; k++) {
            uint32_t a[4];
            LDSM4(a, aoff + k * 32);
            #pragma unroll
            for (int p = 0; p < 6; p++) {
                uint32_t t[4];
                LDSM4T(t, btr + (uint32_t)(k * 16 * 208) + (uint32_t)(p * 32));
                uint32_t b0[2] = {t[0], t[1]}, b1[2] = {t[2], t[3]};
                MMA_F16(acc[2 * p], a, b0);
                MMA_F16(acc[2 * p + 1], a, b1);
            }
        }
        __half* dst = out + (size_t)(b * S_) * D_ + h * HD_;
        const int r = lane >> 2, c0 = (lane & 3) * 2;
        const int i0 = wid * 16 + r, i1 = i0 + 8;
        #pragma unroll
        for (int nf = 0; nf < 12; nf++) {
            int d = nf * 8 + c0;
            if (i0 < S_) {
                __half2 h = __floats2half2_rn(acc[nf][0], acc[nf][1]);
                *(__half2*)(dst + (size_t)i0 * D_ + d) = h;
            }
            if (i1 < S_) {
                __half2 h = __floats2half2_rn(acc[nf][2], acc[nf][3]);
                *(__half2*)(dst + (size_t)i1 * D_ + d) = h;
            }
        }
    }
}

// ---------------- final classifier: split into 4 K-chunks + reduce ----------------
__global__ void fc_partial_kernel(const float* __restrict__ x, const float* __restrict__ Wfc,
                                  float* __restrict__ partial) {
    const int b = blockIdx.x;
    const int z = blockIdx.y;
    const int tid = threadIdx.x;
    const int base = z * 19200;
    const float* xr = x + (size_t)b * (S_ * D_) + base;
    const float* wr = Wfc + 2 * (size_t)base;
    float a0 = 0.f, a1 = 0.f;
    for (int i = tid; i < 19200; i += 256) {
        float v = xr[i];
        a0 += v * wr[2 * i];
        a1 += v * wr[2 * i + 1];
    }
    __shared__ float red[2][8];
    int lane = tid & 31, wid = tid >> 5;
    a0 = warp_sum(a0); a1 = warp_sum(a1);
    if (lane == 0) { red[0][wid] = a0; red[1][wid] = a1; }
    __syncthreads();
    if (wid == 0) {
        float r0 = (lane < 8) ? red[0][lane] : 0.f;
        float r1 = (lane < 8) ? red[1][lane] : 0.f;
        r0 = warp_sum(r0); r1 = warp_sum(r1);
        if (lane == 0) {
            partial[z * 128 + 2 * b + 0] = r0;
            partial[z * 128 + 2 * b + 1] = r1;
        }
    }
}

__global__ void fc_reduce_kernel(const float* __restrict__ partial,
                                 const float* __restrict__ bfc, float* __restrict__ out) {
    int i = threadIdx.x;   // 0..127
    out[i] = partial[i] + partial[128 + i] + partial[256 + i] + partial[384 + i]
           + bfc[i & 1];
}

// ---------------- launch ----------------
extern "C" void kernel_launch(void* const* d_in, const int* in_sizes, int n_in,
                              void* d_out, int out_size) {
    const float* tseq = (const float*)d_in[0];
    const float* pseq = (const float*)d_in[1];
    const float* Wc  = (const float*)d_in[2];
    const float* bc  = (const float*)d_in[3];
    const float* gp  = (const float*)d_in[4];
    const float* bp  = (const float*)d_in[5];
    const float* W1  = (const float*)d_in[6];
    const float* b1  = (const float*)d_in[7];
    const float* W2  = (const float*)d_in[8];
    const float* b2  = (const float*)d_in[9];
    const float* g1  = (const float*)d_in[10];
    const float* bn1 = (const float*)d_in[11];
    const float* g2  = (const float*)d_in[12];
    const float* bn2 = (const float*)d_in[13];
    const float* Wfc = (const float*)d_in[14];
    const float* bfc = (const float*)d_in[15];
    float* out = (float*)d_out;

    float *x, *enc, *pbias, *part, *pe, *fcp;
    __half *xq, *xhi, *attn, *phi, *ffhi;
    __half *w1h, *w2h, *wch;
    cudaGetSymbolAddress((void**)&x, g_x);
    cudaGetSymbolAddress((void**)&enc, g_enc);
    cudaGetSymbolAddress((void**)&pbias, g_pbias);
    cudaGetSymbolAddress((void**)&part, g_part);
    cudaGetSymbolAddress((void**)&pe, g_pe);
    cudaGetSymbolAddress((void**)&fcp, g_fcpart);
    cudaGetSymbolAddress((void**)&xq, g_xq);
    cudaGetSymbolAddress((void**)&xhi, g_xhi);
    cudaGetSymbolAddress((void**)&attn, g_attn);
    cudaGetSymbolAddress((void**)&phi, g_phi);
    cudaGetSymbolAddress((void**)&ffhi, g_ffhi);
    cudaGetSymbolAddress((void**)&w1h, g_w1h);
    cudaGetSymbolAddress((void**)&w2h, g_w2h);
    cudaGetSymbolAddress((void**)&wch, g_wch);
    float* part0 = part;
    float* part1 = part + (size_t)M_ * D_;

    cudaFuncSetAttribute(attn_kernel, cudaFuncAttributeMaxDynamicSharedMemorySize, ATTN_SMEM);
    cudaFuncSetAttribute((mma_gemm<1, 0, 64>), cudaFuncAttributeMaxDynamicSharedMemorySize, GEMM_SMEM_T0_64);
    cudaFuncSetAttribute((mma_gemm<2, 0, 64>), cudaFuncAttributeMaxDynamicSharedMemorySize, GEMM_SMEM_T0_64);

    // weight transpose + fp16 convert (tiny, one-time per launch)
    wconv_kernel<<<dim3(D_ / 32, FF_ / 32), dim3(32, 8)>>>(W1, w1h, D_, FF_);
    wconv_kernel<<<dim3(FF_ / 32, D_ / 32), dim3(32, 8)>>>(W2, w2h, FF_, D_);
    wconv_kernel<<<dim3(D_ / 32, D_ / 32),  dim3(32, 8)>>>(Wc, wch, D_, D_);

    const int total = M_ * D_;
    pe_kernel<<<(S_ * D_ + 255) / 256, 256>>>(pe);
    add_pe_kernel<<<(total + 255) / 256, 256>>>(tseq, pe, x, xq);
    pool_kernel<<<(total + 255) / 256, 256>>>(pseq, phi);

    // param encoder: enc = LN(pooled @ Wc + bc)  (single-fp16 A, split-K=2)
    mma_gemm<2, 0, 64><<<dim3(D_ / BNT, M_ / BMT, 2), 256, GEMM_SMEM_T0_64>>>(
        phi, nullptr, wch, nullptr, part0, nullptr, M_, D_, D_);
    ln_kernel<0><<<M_, 192>>>(part0, part1, nullptr, nullptr, bc, gp, bp, enc, nullptr);

    // layer-invariant attention bias
    pbias_kernel<<<B_ * H_, 256>>>(enc, pbias);

    for (int l = 0; l < NLAYERS; l++) {
        attn_kernel<<<B_ * H_, 256, ATTN_SMEM>>>(xq, pbias, attn);
        ln_kernel<1><<<M_, 192>>>(x, nullptr, nullptr, attn, nullptr, g1, bn1, x, xhi);
        // FFN1: single-fp16 A, gelu -> single fp16 ff   (BKS=64)
        mma_gemm<1, 0, 64><<<dim3(FF_ / BNT, M_ / BMT), 256, GEMM_SMEM_T0_64>>>(
            xhi, nullptr, w1h, b1, nullptr, ffhi, M_, FF_, D_);
        // FFN2: single-fp16 A, split-K=2 -> two fp32 partials, b2 folded into LN
        mma_gemm<2, 0, 64><<<dim3(D_ / BNT, M_ / BMT, 2), 256, GEMM_SMEM_T0_64>>>(
            ffhi, nullptr, w2h, nullptr, part0, nullptr, M_, D_, FF_);
        // end-of-layer LN: x + 2 partials + b2; fp32 x + fp16 copy for next attn
        ln_kernel<1><<<M_, 192>>>(x, part0, part1, nullptr, b2, g2, bn2, x, xq);
    }

    fc_partial_kernel<<<dim3(B_, 4), 256>>>(x, Wfc, fcp);
    fc_reduce_kernel<<<1, 128>>>(fcp, bfc, out);
}